// round 11
// baseline (speedup 1.0000x reference)
#include <cuda_runtime.h>
#include <cuda_fp16.h>
#include <math.h>
#include <stdint.h>

// ---------------- problem constants ----------------
#define BB 2
#define LL 2048
#define HH 1536
#define II 3072
#define NN 16
#define RR 96
#define MTOT 4096
#define E2 6144
#define PP 128
#define SPLITK 8

// ---------------- fp32 scratch ----------------
__device__ __align__(256) float g_proj[(size_t)MTOT * E2];
__device__ __align__(256) float g_x[(size_t)MTOT * II];
__device__ __align__(256) float g_ssmp[(size_t)MTOT * PP];
__device__ __align__(256) float g_delta[(size_t)MTOT * II];
__device__ __align__(256) float g_part[SPLITK * (size_t)MTOT * PP];
__device__ __align__(256) float g_opart[2 * (size_t)MTOT * HH];   // out_proj split-K partials

// ---------------- fp16 scratch ----------------
__device__ __align__(256) __half g_hs16[(size_t)MTOT * HH];
__device__ __align__(256) __half g_Win16[(size_t)E2 * HH];
__device__ __align__(256) __half g_x16[(size_t)MTOT * II];
__device__ __align__(256) __half g_Wx16[(size_t)PP * II];
__device__ __align__(256) __half g_sp16[(size_t)MTOT * PP];
__device__ __align__(256) __half g_Wdt16[(size_t)II * PP];   // K padded 96->128
__device__ __align__(256) __half g_y16[(size_t)MTOT * II];
__device__ __align__(256) __half g_Wout16[(size_t)HH * II];

// ---------------- helpers ----------------
__device__ __forceinline__ float fast_ex2(float x) {
    float r; asm("ex2.approx.f32 %0, %1;" : "=f"(r) : "f"(x)); return r;
}
__device__ __forceinline__ uint32_t smem_u32(const void* p) {
    return (uint32_t)__cvta_generic_to_shared(p);
}
__device__ __forceinline__ void cp16(void* dst_smem, const void* src_gmem) {
    unsigned d = smem_u32(dst_smem);
    asm volatile("cp.async.cg.shared.global [%0], [%1], 16;" :: "r"(d), "l"(src_gmem));
}
__device__ __forceinline__ void cp_commit() { asm volatile("cp.async.commit_group;"); }
__device__ __forceinline__ void cp_wait1() { asm volatile("cp.async.wait_group 1;" ::: "memory"); }
__device__ __forceinline__ void cp_wait0() { asm volatile("cp.async.wait_group 0;" ::: "memory"); }

__device__ __forceinline__ void ldsm4(uint32_t& r0, uint32_t& r1, uint32_t& r2, uint32_t& r3,
                                      uint32_t addr) {
    asm volatile("ldmatrix.sync.aligned.m8n8.x4.shared.b16 {%0,%1,%2,%3}, [%4];"
                 : "=r"(r0), "=r"(r1), "=r"(r2), "=r"(r3) : "r"(addr));
}
__device__ __forceinline__ void mma16816(float* d, const uint32_t* a, const uint32_t* b) {
    asm volatile("mma.sync.aligned.m16n8k16.row.col.f32.f16.f16.f32 "
                 "{%0,%1,%2,%3}, {%4,%5,%6,%7}, {%8,%9}, {%0,%1,%2,%3};"
                 : "+f"(d[0]), "+f"(d[1]), "+f"(d[2]), "+f"(d[3])
                 : "r"(a[0]), "r"(a[1]), "r"(a[2]), "r"(a[3]), "r"(b[0]), "r"(b[1]));
}
__device__ __forceinline__ uint32_t pack2(float a, float b) {
    __half2 h = __floats2half2_rn(a, b);
    return *(uint32_t*)&h;
}

// ============================================================================
// fp16 single-pass GEMM: C[M,N] = A[M,K] * B[N,K]^T, fp32 accum.
// 128x128 CTA tile, BK=64, 3-stage cp.async, 8 warps (2m x 4n), warp 64x32.
// __launch_bounds__(256, 2). Split-K via blockIdx.z (partials at
// C + z*c_part_stride). EPI==1: softplus(C + bias[col]).
// ============================================================================
#define TILE_B 16384
#define STAGE_B (2 * TILE_B)
#define GEMM_SMEM (3 * STAGE_B)

template <int EPI>
__global__ __launch_bounds__(256, 2)
void gemm_mma(const __half* __restrict__ A, const __half* __restrict__ B,
              int K, float* __restrict__ C, int ldc,
              size_t c_part_stride, const float* __restrict__ bias) {
    extern __shared__ char smem[];
    const int tid = threadIdx.x;
    const int lane = tid & 31;
    const int wid = tid >> 5;
    const int m0 = blockIdx.y * 128;
    const int n0 = blockIdx.x * 128;
    const int wm = (wid & 1) * 64;
    const int wn = (wid >> 1) * 32;
    const int ncz = (K >> 6) / gridDim.z;
    const int c0 = blockIdx.z * ncz;
    C += (size_t)blockIdx.z * c_part_stride;

    float acc[4][4][4] = {};

    auto issue = [&](int lc) {
        char* st = smem + (lc % 3) * STAGE_B;
        const int k0 = (c0 + lc) << 6;
#pragma unroll
        for (int rep = 0; rep < 4; rep++) {
            int idx = tid + rep * 256;
            int r = idx >> 3;
            int cc = idx & 7;
            uint32_t so = (uint32_t)(r * 128 + ((cc ^ (r & 7)) * 16));
            cp16(st + so, A + (size_t)(m0 + r) * K + k0 + cc * 8);
            cp16(st + TILE_B + so, B + (size_t)(n0 + r) * K + k0 + cc * 8);
        }
    };

    issue(0); cp_commit();
    if (ncz > 1) issue(1);
    cp_commit();

    const int a_row = lane & 15;
    const int a_kh = lane >> 4;
    const int b_nr = (lane & 7) + ((lane >> 4) << 3);
    const int b_kh = (lane >> 3) & 1;

    for (int lc = 0; lc < ncz; lc++) {
        cp_wait1();
        __syncthreads();
        if (lc + 2 < ncz) issue(lc + 2);
        cp_commit();

        const uint32_t sA = smem_u32(smem + (lc % 3) * STAGE_B);
        const uint32_t sB = sA + TILE_B;

#pragma unroll
        for (int kc = 0; kc < 8; kc += 2) {
            uint32_t bf[4][2];
            uint32_t af[4][4];
#pragma unroll
            for (int jj = 0; jj < 2; jj++) {
                int r = wn + b_nr + jj * 16;
                uint32_t off = (uint32_t)(r * 128 + (((kc + b_kh) ^ (r & 7)) * 16));
                uint32_t t0, t1, t2, t3;
                ldsm4(t0, t1, t2, t3, sB + off);
                bf[jj * 2][0] = t0; bf[jj * 2][1] = t1;
                bf[jj * 2 + 1][0] = t2; bf[jj * 2 + 1][1] = t3;
            }
#pragma unroll
            for (int i = 0; i < 4; i++) {
                int r = wm + i * 16 + a_row;
                uint32_t off = (uint32_t)(r * 128 + (((kc + a_kh) ^ (r & 7)) * 16));
                ldsm4(af[i][0], af[i][1], af[i][2], af[i][3], sA + off);
            }
#pragma unroll
            for (int i = 0; i < 4; i++)
#pragma unroll
                for (int j = 0; j < 4; j++)
                    mma16816(acc[i][j], af[i], bf[j]);
        }
    }

    // epilogue
    const int quad = lane >> 2;
    const int tq = lane & 3;
#pragma unroll
    for (int i = 0; i < 4; i++) {
#pragma unroll
        for (int j = 0; j < 4; j++) {
            int r0 = m0 + wm + i * 16 + quad;
            int cc = n0 + wn + j * 8 + tq * 2;
            float v0 = acc[i][j][0], v1 = acc[i][j][1];
            float v2 = acc[i][j][2], v3 = acc[i][j][3];
            if (EPI == 1) {
                float b0 = bias[cc], b1 = bias[cc + 1];
                v0 += b0; v1 += b1; v2 += b0; v3 += b1;
                v0 = (v0 > 20.0f) ? v0 : log1pf(__expf(v0));
                v1 = (v1 > 20.0f) ? v1 : log1pf(__expf(v1));
                v2 = (v2 > 20.0f) ? v2 : log1pf(__expf(v2));
                v3 = (v3 > 20.0f) ? v3 : log1pf(__expf(v3));
            }
            *(float2*)(C + (size_t)r0 * ldc + cc) = make_float2(v0, v1);
            *(float2*)(C + (size_t)(r0 + 8) * ldc + cc) = make_float2(v2, v3);
        }
    }
}

// ============================================================================
// conversion kernels (vectorized: 4 elems/thread)
// ============================================================================
__global__ void convert16_kernel(const float4* __restrict__ src,
                                 uint2* __restrict__ dst, int n4) {
    int i = blockIdx.x * blockDim.x + threadIdx.x;
    if (i >= n4) return;
    float4 v = src[i];
    uint2 o;
    o.x = pack2(v.x, v.y);
    o.y = pack2(v.z, v.w);
    dst[i] = o;
}

// W_dt [3072,96] -> fp16 [3072,128] zero-padded in K (4 elems/thread)
__global__ void convert_wdt_kernel(const float* __restrict__ src,
                                   uint2* __restrict__ dst) {
    int idx = blockIdx.x * blockDim.x + threadIdx.x;
    if (idx >= II * 32) return;
    int k4 = (idx & 31) * 4;
    int i = idx >> 5;
    float v[4];
#pragma unroll
    for (int t = 0; t < 4; t++)
        v[t] = (k4 + t < RR) ? src[i * RR + k4 + t] : 0.0f;
    uint2 o;
    o.x = pack2(v[0], v[1]);
    o.y = pack2(v[2], v[3]);
    dst[idx] = o;
}

// x_proj partial reduce + fp16 convert (4 elems/thread)
__global__ void reduce_ssmp_kernel() {
    int idx = blockIdx.x * blockDim.x + threadIdx.x;
    if (idx >= MTOT * PP / 4) return;
    const size_t s4 = (size_t)MTOT * PP / 4;
    const float4* p = (const float4*)g_part;
    float4 a = p[idx];
#pragma unroll
    for (int z = 1; z < SPLITK; z++) {
        float4 b = p[z * s4 + idx];
        a.x += b.x; a.y += b.y; a.z += b.z; a.w += b.w;
    }
    ((float4*)g_ssmp)[idx] = a;
    uint2 o; o.x = pack2(a.x, a.y); o.y = pack2(a.z, a.w);
    ((uint2*)g_sp16)[idx] = o;
}

// out_proj split-K(2) reduce -> d_out (float4)
__global__ void reduce_out_kernel(float4* __restrict__ out) {
    int idx = blockIdx.x * blockDim.x + threadIdx.x;
    if (idx >= MTOT * HH / 4) return;
    const size_t s4 = (size_t)MTOT * HH / 4;
    const float4* p = (const float4*)g_opart;
    float4 a = p[idx];
    float4 b = p[s4 + idx];
    a.x += b.x; a.y += b.y; a.z += b.z; a.w += b.w;
    out[idx] = a;
}

// ============================================================================
// causal depthwise conv1d (K=4) + SiLU; 4 timesteps per thread
// ============================================================================
__global__ void conv_silu_kernel(const float* __restrict__ conv_w,
                                 const float* __restrict__ conv_b) {
    int idx = blockIdx.x * blockDim.x + threadIdx.x;
    if (idx >= (MTOT / 4) * II) return;
    const int i = idx % II;
    const int t = idx / II;
    const int m0 = t * 4;
    const int l0 = m0 & (LL - 1);

    float w0 = conv_w[i * 4 + 0], w1 = conv_w[i * 4 + 1];
    float w2 = conv_w[i * 4 + 2], w3 = conv_w[i * 4 + 3];
    const float cb = conv_b[i];

    float v[7];
#pragma unroll
    for (int j = 0; j < 7; j++) {
        int l = l0 - 3 + j;
        v[j] = (l >= 0) ? g_proj[(size_t)(m0 - 3 + j) * E2 + i] : 0.0f;
    }
#pragma unroll
    for (int s = 0; s < 4; s++) {
        float acc = fmaf(v[s], w0, fmaf(v[s + 1], w1, fmaf(v[s + 2], w2, fmaf(v[s + 3], w3, cb))));
        float o = acc / (1.0f + __expf(-acc));
        size_t off = (size_t)(m0 + s) * II + i;
        g_x[off] = o;
        g_x16[off] = __float2half(o);
    }
}

// ============================================================================
// Selective scan + D-skip + gate*silu(gate); all inputs staged via cp.async.
// ============================================================================
#define SCH 32
#define NCHUNK (LL / SCH)

__global__ __launch_bounds__(128)
void scan_kernel(const float* __restrict__ Amat, const float* __restrict__ Dvec) {
    __shared__ __align__(16) float sD[2][SCH * 32];
    __shared__ __align__(16) float sX[2][SCH * 32];
    __shared__ __align__(16) float sBC[2][SCH * 32];
    __shared__ __align__(16) float sG[2][SCH * 32];
    __shared__ __align__(16) float sY[SCH * 32];

    const int tid = threadIdx.x;
    const int blk = blockIdx.x;
    const int b = blk / 96;
    const int ibase = (blk % 96) * 32;
    const int q = tid & 3;
    const int c = tid >> 2;
    const int i = ibase + c;
    const int mbase = b * LL;

    float a2[4];
#pragma unroll
    for (int n = 0; n < 4; n++)
        a2[n] = Amat[i * NN + q * 4 + n] * 1.4426950408889634f;
    const float dv = Dvec[i];
    float st[4] = {0.0f, 0.0f, 0.0f, 0.0f};

    auto issue = [&](int buf, int ch) {
        const int m0 = mbase + ch * SCH;
#pragma unroll
        for (int k2 = 0; k2 < 2; k2++) {
            int f = tid + k2 * 128;
            int l = f >> 3;
            int c4 = (f & 7) * 4;
            int m = m0 + l;
            cp16(&sD[buf][l * 32 + c4], &g_delta[(size_t)m * II + ibase + c4]);
            cp16(&sX[buf][l * 32 + c4], &g_x[(size_t)m * II + ibase + c4]);
            cp16(&sBC[buf][l * 32 + c4], &g_ssmp[(size_t)m * PP + RR + c4]);
            cp16(&sG[buf][l * 32 + c4], &g_proj[(size_t)m * E2 + II + ibase + c4]);
        }
    };

    issue(0, 0);
    cp_commit();

    for (int ch = 0; ch < NCHUNK; ch++) {
        const int cur = ch & 1;
        if (ch + 1 < NCHUNK) {
            issue(1 - cur, ch + 1);
            cp_commit();
            cp_wait1();
        } else {
            cp_wait0();
        }
        __syncthreads();

        const int m0 = mbase + ch * SCH;
#pragma unroll 4
        for (int l = 0; l < SCH; l++) {
            const float delta = sD[cur][l * 32 + c];
            const float xv = sX[cur][l * 32 + c];
            const float du = delta * xv;
            const float4 Bv = *(const float4*)&sBC[cur][l * 32 + q * 4];
            const float4 Cv = *(const float4*)&sBC[cur][l * 32 + 16 + q * 4];
            float dA0 = fast_ex2(delta * a2[0]);
            float dA1 = fast_ex2(delta * a2[1]);
            float dA2 = fast_ex2(delta * a2[2]);
            float dA3 = fast_ex2(delta * a2[3]);
            st[0] = fmaf(st[0], dA0, du * Bv.x);
            st[1] = fmaf(st[1], dA1, du * Bv.y);
            st[2] = fmaf(st[2], dA2, du * Bv.z);
            st[3] = fmaf(st[3], dA3, du * Bv.w);
            float y = st[0] * Cv.x + st[1] * Cv.y + st[2] * Cv.z + st[3] * Cv.w;
            y += __shfl_xor_sync(0xffffffffu, y, 1);
            y += __shfl_xor_sync(0xffffffffu, y, 2);
            if (q == 0) {
                const float g = sG[cur][l * 32 + c];
                const float sg = g / (1.0f + __expf(-g));
                sY[l * 32 + c] = (y + xv * dv) * sg;
            }
        }
        __syncthreads();

#pragma unroll
        for (int k2 = 0; k2 < 4; k2++) {
            int f = tid + k2 * 128;
            int l = f >> 4;
            int c2 = (f & 15) * 2;
            __half2 p = __floats2half2_rn(sY[l * 32 + c2], sY[l * 32 + c2 + 1]);
            *(__half2*)&g_y16[(size_t)(m0 + l) * II + ibase + c2] = p;
        }
    }
}

// ============================================================================
// kernel_launch
// ============================================================================
extern "C" void kernel_launch(void* const* d_in, const int* in_sizes, int n_in,
                              void* d_out, int out_size) {
    const float* hs      = (const float*)d_in[0];
    const float* W_in    = (const float*)d_in[1];
    const float* conv_w  = (const float*)d_in[2];
    const float* conv_b  = (const float*)d_in[3];
    const float* W_x     = (const float*)d_in[4];
    const float* W_dt    = (const float*)d_in[5];
    const float* dt_bias = (const float*)d_in[6];
    const float* Amat    = (const float*)d_in[7];
    const float* Dvec    = (const float*)d_in[8];
    const float* W_out   = (const float*)d_in[9];
    float* out = (float*)d_out;

    float *proj, *delta, *part, *opart;
    cudaGetSymbolAddress((void**)&proj, g_proj);
    cudaGetSymbolAddress((void**)&delta, g_delta);
    cudaGetSymbolAddress((void**)&part, g_part);
    cudaGetSymbolAddress((void**)&opart, g_opart);
    __half *hs16, *Win16, *x16, *Wx16, *sp16, *Wdt16, *y16, *Wout16;
    cudaGetSymbolAddress((void**)&hs16, g_hs16);
    cudaGetSymbolAddress((void**)&Win16, g_Win16);
    cudaGetSymbolAddress((void**)&x16, g_x16);
    cudaGetSymbolAddress((void**)&Wx16, g_Wx16);
    cudaGetSymbolAddress((void**)&sp16, g_sp16);
    cudaGetSymbolAddress((void**)&Wdt16, g_Wdt16);
    cudaGetSymbolAddress((void**)&y16, g_y16);
    cudaGetSymbolAddress((void**)&Wout16, g_Wout16);

    cudaFuncSetAttribute(gemm_mma<0>, cudaFuncAttributeMaxDynamicSharedMemorySize, GEMM_SMEM);
    cudaFuncSetAttribute(gemm_mma<1>, cudaFuncAttributeMaxDynamicSharedMemorySize, GEMM_SMEM);

    // -- launches 1..3: conversions needed before/with in_proj --
    {
        int n4;
        n4 = MTOT * HH / 4;
        convert16_kernel<<<(n4 + 255) / 256, 256>>>((const float4*)hs, (uint2*)hs16, n4);
        n4 = E2 * HH / 4;
        convert16_kernel<<<(n4 + 255) / 256, 256>>>((const float4*)W_in, (uint2*)Win16, n4);
        n4 = PP * II / 4;
        convert16_kernel<<<(n4 + 255) / 256, 256>>>((const float4*)W_x, (uint2*)Wx16, n4);
    }

    // -- launch 4: in_proj GEMM (positioned here so ncu's skip-3 capture
    //    profiles the dominant GEMM) --
    gemm_mma<0><<<dim3(E2 / 128, MTOT / 128, 1), 256, GEMM_SMEM>>>(
        hs16, Win16, HH, proj, E2, 0, nullptr);

    // remaining conversions (independent of in_proj output)
    {
        int n4;
        n4 = HH * II / 4;
        convert16_kernel<<<(n4 + 255) / 256, 256>>>((const float4*)W_out, (uint2*)Wout16, n4);
        n4 = II * 32;
        convert_wdt_kernel<<<(n4 + 255) / 256, 256>>>(W_dt, (uint2*)Wdt16);
    }

    // conv + SiLU
    {
        int total = (MTOT / 4) * II;
        conv_silu_kernel<<<(total + 255) / 256, 256>>>(conv_w, conv_b);
    }

    // x_proj split-K(8): partials = x @ W_x^T  (K=3072)
    gemm_mma<0><<<dim3(1, MTOT / 128, SPLITK), 256, GEMM_SMEM>>>(
        x16, Wx16, II, part, PP, (size_t)MTOT * PP, nullptr);
    {
        int n4 = MTOT * PP / 4;
        reduce_ssmp_kernel<<<(n4 + 255) / 256, 256>>>();
    }

    // dt_proj + softplus  (K=128 padded)
    gemm_mma<1><<<dim3(II / 128, MTOT / 128, 1), 256, GEMM_SMEM>>>(
        sp16, Wdt16, 128, delta, II, 0, dt_bias);

    // scan -> y fp16
    scan_kernel<<<192, 128>>>(Amat, Dvec);

    // out_proj split-K(2): partials = y @ W_out^T  (K=3072)
    gemm_mma<0><<<dim3(HH / 128, MTOT / 128, 2), 256, GEMM_SMEM>>>(
        y16, Wout16, II, opart, HH, (size_t)MTOT * HH, nullptr);
    {
        int n4 = MTOT * HH / 4;
        reduce_out_kernel<<<(n4 + 255) / 256, 256>>>((float4*)out);
    }
}

// round 12
// speedup vs baseline: 1.0056x; 1.0056x over previous
#include <cuda_runtime.h>
#include <cuda_fp16.h>
#include <math.h>
#include <stdint.h>

// ---------------- problem constants ----------------
#define BB 2
#define LL 2048
#define HH 1536
#define II 3072
#define NN 16
#define RR 96
#define MTOT 4096
#define E2 6144
#define PP 128
#define SPLITK 8

// ---------------- fp32 scratch ----------------
__device__ __align__(256) float g_proj[(size_t)MTOT * E2];
__device__ __align__(256) float g_x[(size_t)MTOT * II];
__device__ __align__(256) float g_ssmp[(size_t)MTOT * PP];
__device__ __align__(256) float g_delta[(size_t)MTOT * II];
__device__ __align__(256) float g_part[SPLITK * (size_t)MTOT * PP];

// ---------------- fp16 scratch ----------------
__device__ __align__(256) __half g_hs16[(size_t)MTOT * HH];
__device__ __align__(256) __half g_Win16[(size_t)E2 * HH];
__device__ __align__(256) __half g_x16[(size_t)MTOT * II];
__device__ __align__(256) __half g_Wx16[(size_t)PP * II];
__device__ __align__(256) __half g_sp16[(size_t)MTOT * PP];
__device__ __align__(256) __half g_Wdt16[(size_t)II * PP];   // K padded 96->128
__device__ __align__(256) __half g_y16[(size_t)MTOT * II];
__device__ __align__(256) __half g_Wout16[(size_t)HH * II];

// ---------------- helpers ----------------
__device__ __forceinline__ float fast_ex2(float x) {
    float r; asm("ex2.approx.f32 %0, %1;" : "=f"(r) : "f"(x)); return r;
}
__device__ __forceinline__ uint32_t smem_u32(const void* p) {
    return (uint32_t)__cvta_generic_to_shared(p);
}
__device__ __forceinline__ void cp16(void* dst_smem, const void* src_gmem) {
    unsigned d = smem_u32(dst_smem);
    asm volatile("cp.async.cg.shared.global [%0], [%1], 16;" :: "r"(d), "l"(src_gmem));
}
__device__ __forceinline__ void cp_commit() { asm volatile("cp.async.commit_group;"); }
__device__ __forceinline__ void cp_wait1() { asm volatile("cp.async.wait_group 1;" ::: "memory"); }
__device__ __forceinline__ void cp_wait0() { asm volatile("cp.async.wait_group 0;" ::: "memory"); }

__device__ __forceinline__ void ldsm4(uint32_t& r0, uint32_t& r1, uint32_t& r2, uint32_t& r3,
                                      uint32_t addr) {
    asm volatile("ldmatrix.sync.aligned.m8n8.x4.shared.b16 {%0,%1,%2,%3}, [%4];"
                 : "=r"(r0), "=r"(r1), "=r"(r2), "=r"(r3) : "r"(addr));
}
__device__ __forceinline__ void mma16816(float* d, const uint32_t* a, const uint32_t* b) {
    asm volatile("mma.sync.aligned.m16n8k16.row.col.f32.f16.f16.f32 "
                 "{%0,%1,%2,%3}, {%4,%5,%6,%7}, {%8,%9}, {%0,%1,%2,%3};"
                 : "+f"(d[0]), "+f"(d[1]), "+f"(d[2]), "+f"(d[3])
                 : "r"(a[0]), "r"(a[1]), "r"(a[2]), "r"(a[3]), "r"(b[0]), "r"(b[1]));
}
__device__ __forceinline__ uint32_t pack2(float a, float b) {
    __half2 h = __floats2half2_rn(a, b);
    return *(uint32_t*)&h;
}

// ============================================================================
// fp16 single-pass GEMM: C[M,N] = A[M,K] * B[N,K]^T, fp32 accum.
// 128x128 CTA tile, BK=64, 3-stage cp.async, 8 warps (2m x 4n), warp 64x32.
// Register double-buffered fragments: ldsm for kc+1 overlaps MMAs of kc.
// __launch_bounds__(256, 2). Split-K via blockIdx.z.
// EPI==1: softplus(C + bias[col]).
// ============================================================================
#define TILE_B 16384
#define STAGE_B (2 * TILE_B)
#define GEMM_SMEM (3 * STAGE_B)

template <int EPI>
__global__ __launch_bounds__(256, 2)
void gemm_mma(const __half* __restrict__ A, const __half* __restrict__ B,
              int K, float* __restrict__ C, int ldc,
              size_t c_part_stride, const float* __restrict__ bias) {
    extern __shared__ char smem[];
    const int tid = threadIdx.x;
    const int lane = tid & 31;
    const int wid = tid >> 5;
    const int m0 = blockIdx.y * 128;
    const int n0 = blockIdx.x * 128;
    const int wm = (wid & 1) * 64;
    const int wn = (wid >> 1) * 32;
    const int ncz = (K >> 6) / gridDim.z;
    const int c0 = blockIdx.z * ncz;
    C += (size_t)blockIdx.z * c_part_stride;

    float acc[4][4][4] = {};

    auto issue = [&](int lc) {
        char* st = smem + (lc % 3) * STAGE_B;
        const int k0 = (c0 + lc) << 6;
#pragma unroll
        for (int rep = 0; rep < 4; rep++) {
            int idx = tid + rep * 256;
            int r = idx >> 3;
            int cc = idx & 7;
            uint32_t so = (uint32_t)(r * 128 + ((cc ^ (r & 7)) * 16));
            cp16(st + so, A + (size_t)(m0 + r) * K + k0 + cc * 8);
            cp16(st + TILE_B + so, B + (size_t)(n0 + r) * K + k0 + cc * 8);
        }
    };

    issue(0); cp_commit();
    if (ncz > 1) issue(1);
    cp_commit();

    const int a_row = lane & 15;
    const int a_kh = lane >> 4;
    const int b_nr = (lane & 7) + ((lane >> 4) << 3);
    const int b_kh = (lane >> 3) & 1;

    uint32_t af[2][4][4], bf[2][4][2];

    // fragment loader for k-step kk (kc = 2*kk) from stage base sA
    auto load_frags = [&](uint32_t sA, uint32_t sB, int kk, int buf) {
        const int kc = kk * 2;
#pragma unroll
        for (int jj = 0; jj < 2; jj++) {
            int r = wn + b_nr + jj * 16;
            uint32_t off = (uint32_t)(r * 128 + (((kc + b_kh) ^ (r & 7)) * 16));
            uint32_t t0, t1, t2, t3;
            ldsm4(t0, t1, t2, t3, sB + off);
            bf[buf][jj * 2][0] = t0; bf[buf][jj * 2][1] = t1;
            bf[buf][jj * 2 + 1][0] = t2; bf[buf][jj * 2 + 1][1] = t3;
        }
#pragma unroll
        for (int i = 0; i < 4; i++) {
            int r = wm + i * 16 + a_row;
            uint32_t off = (uint32_t)(r * 128 + (((kc + a_kh) ^ (r & 7)) * 16));
            ldsm4(af[buf][i][0], af[buf][i][1], af[buf][i][2], af[buf][i][3], sA + off);
        }
    };

    for (int lc = 0; lc < ncz; lc++) {
        cp_wait1();
        __syncthreads();
        if (lc + 2 < ncz) issue(lc + 2);
        cp_commit();

        const uint32_t sA = smem_u32(smem + (lc % 3) * STAGE_B);
        const uint32_t sB = sA + TILE_B;

        load_frags(sA, sB, 0, 0);
#pragma unroll
        for (int kk = 0; kk < 4; kk++) {
            if (kk < 3) load_frags(sA, sB, kk + 1, (kk + 1) & 1);
            const int cur = kk & 1;
#pragma unroll
            for (int i = 0; i < 4; i++)
#pragma unroll
                for (int j = 0; j < 4; j++)
                    mma16816(acc[i][j], af[cur][i], bf[cur][j]);
        }
    }

    // epilogue
    const int quad = lane >> 2;
    const int tq = lane & 3;
#pragma unroll
    for (int i = 0; i < 4; i++) {
#pragma unroll
        for (int j = 0; j < 4; j++) {
            int r0 = m0 + wm + i * 16 + quad;
            int cc = n0 + wn + j * 8 + tq * 2;
            float v0 = acc[i][j][0], v1 = acc[i][j][1];
            float v2 = acc[i][j][2], v3 = acc[i][j][3];
            if (EPI == 1) {
                float b0 = bias[cc], b1 = bias[cc + 1];
                v0 += b0; v1 += b1; v2 += b0; v3 += b1;
                v0 = (v0 > 20.0f) ? v0 : log1pf(__expf(v0));
                v1 = (v1 > 20.0f) ? v1 : log1pf(__expf(v1));
                v2 = (v2 > 20.0f) ? v2 : log1pf(__expf(v2));
                v3 = (v3 > 20.0f) ? v3 : log1pf(__expf(v3));
            }
            *(float2*)(C + (size_t)r0 * ldc + cc) = make_float2(v0, v1);
            *(float2*)(C + (size_t)(r0 + 8) * ldc + cc) = make_float2(v2, v3);
        }
    }
}

// ============================================================================
// conversion kernels (vectorized: 4 elems/thread)
// ============================================================================
__global__ void convert16_kernel(const float4* __restrict__ src,
                                 uint2* __restrict__ dst, int n4) {
    int i = blockIdx.x * blockDim.x + threadIdx.x;
    if (i >= n4) return;
    float4 v = src[i];
    uint2 o;
    o.x = pack2(v.x, v.y);
    o.y = pack2(v.z, v.w);
    dst[i] = o;
}

// W_dt [3072,96] -> fp16 [3072,128] zero-padded in K (4 elems/thread)
__global__ void convert_wdt_kernel(const float* __restrict__ src,
                                   uint2* __restrict__ dst) {
    int idx = blockIdx.x * blockDim.x + threadIdx.x;
    if (idx >= II * 32) return;
    int k4 = (idx & 31) * 4;
    int i = idx >> 5;
    float v[4];
#pragma unroll
    for (int t = 0; t < 4; t++)
        v[t] = (k4 + t < RR) ? src[i * RR + k4 + t] : 0.0f;
    uint2 o;
    o.x = pack2(v[0], v[1]);
    o.y = pack2(v[2], v[3]);
    dst[idx] = o;
}

// x_proj partial reduce + fp16 convert (4 elems/thread)
__global__ void reduce_ssmp_kernel() {
    int idx = blockIdx.x * blockDim.x + threadIdx.x;
    if (idx >= MTOT * PP / 4) return;
    const size_t s4 = (size_t)MTOT * PP / 4;
    const float4* p = (const float4*)g_part;
    float4 a = p[idx];
#pragma unroll
    for (int z = 1; z < SPLITK; z++) {
        float4 b = p[z * s4 + idx];
        a.x += b.x; a.y += b.y; a.z += b.z; a.w += b.w;
    }
    ((float4*)g_ssmp)[idx] = a;
    uint2 o; o.x = pack2(a.x, a.y); o.y = pack2(a.z, a.w);
    ((uint2*)g_sp16)[idx] = o;
}

// ============================================================================
// causal depthwise conv1d (K=4) + SiLU; 4 timesteps per thread
// ============================================================================
__global__ void conv_silu_kernel(const float* __restrict__ conv_w,
                                 const float* __restrict__ conv_b) {
    int idx = blockIdx.x * blockDim.x + threadIdx.x;
    if (idx >= (MTOT / 4) * II) return;
    const int i = idx % II;
    const int t = idx / II;
    const int m0 = t * 4;
    const int l0 = m0 & (LL - 1);

    float w0 = conv_w[i * 4 + 0], w1 = conv_w[i * 4 + 1];
    float w2 = conv_w[i * 4 + 2], w3 = conv_w[i * 4 + 3];
    const float cb = conv_b[i];

    float v[7];
#pragma unroll
    for (int j = 0; j < 7; j++) {
        int l = l0 - 3 + j;
        v[j] = (l >= 0) ? g_proj[(size_t)(m0 - 3 + j) * E2 + i] : 0.0f;
    }
#pragma unroll
    for (int s = 0; s < 4; s++) {
        float acc = fmaf(v[s], w0, fmaf(v[s + 1], w1, fmaf(v[s + 2], w2, fmaf(v[s + 3], w3, cb))));
        float o = acc / (1.0f + __expf(-acc));
        size_t off = (size_t)(m0 + s) * II + i;
        g_x[off] = o;
        g_x16[off] = __float2half(o);
    }
}

// ============================================================================
// Selective scan + D-skip + gate*silu(gate); all inputs staged via cp.async.
// ============================================================================
#define SCH 32
#define NCHUNK (LL / SCH)

__global__ __launch_bounds__(128)
void scan_kernel(const float* __restrict__ Amat, const float* __restrict__ Dvec) {
    __shared__ __align__(16) float sD[2][SCH * 32];
    __shared__ __align__(16) float sX[2][SCH * 32];
    __shared__ __align__(16) float sBC[2][SCH * 32];
    __shared__ __align__(16) float sG[2][SCH * 32];
    __shared__ __align__(16) float sY[SCH * 32];

    const int tid = threadIdx.x;
    const int blk = blockIdx.x;
    const int b = blk / 96;
    const int ibase = (blk % 96) * 32;
    const int q = tid & 3;
    const int c = tid >> 2;
    const int i = ibase + c;
    const int mbase = b * LL;

    float a2[4];
#pragma unroll
    for (int n = 0; n < 4; n++)
        a2[n] = Amat[i * NN + q * 4 + n] * 1.4426950408889634f;
    const float dv = Dvec[i];
    float st[4] = {0.0f, 0.0f, 0.0f, 0.0f};

    auto issue = [&](int buf, int ch) {
        const int m0 = mbase + ch * SCH;
#pragma unroll
        for (int k2 = 0; k2 < 2; k2++) {
            int f = tid + k2 * 128;
            int l = f >> 3;
            int c4 = (f & 7) * 4;
            int m = m0 + l;
            cp16(&sD[buf][l * 32 + c4], &g_delta[(size_t)m * II + ibase + c4]);
            cp16(&sX[buf][l * 32 + c4], &g_x[(size_t)m * II + ibase + c4]);
            cp16(&sBC[buf][l * 32 + c4], &g_ssmp[(size_t)m * PP + RR + c4]);
            cp16(&sG[buf][l * 32 + c4], &g_proj[(size_t)m * E2 + II + ibase + c4]);
        }
    };

    issue(0, 0);
    cp_commit();

    for (int ch = 0; ch < NCHUNK; ch++) {
        const int cur = ch & 1;
        if (ch + 1 < NCHUNK) {
            issue(1 - cur, ch + 1);
            cp_commit();
            cp_wait1();
        } else {
            cp_wait0();
        }
        __syncthreads();

        const int m0 = mbase + ch * SCH;
#pragma unroll 4
        for (int l = 0; l < SCH; l++) {
            const float delta = sD[cur][l * 32 + c];
            const float xv = sX[cur][l * 32 + c];
            const float du = delta * xv;
            const float4 Bv = *(const float4*)&sBC[cur][l * 32 + q * 4];
            const float4 Cv = *(const float4*)&sBC[cur][l * 32 + 16 + q * 4];
            float dA0 = fast_ex2(delta * a2[0]);
            float dA1 = fast_ex2(delta * a2[1]);
            float dA2 = fast_ex2(delta * a2[2]);
            float dA3 = fast_ex2(delta * a2[3]);
            st[0] = fmaf(st[0], dA0, du * Bv.x);
            st[1] = fmaf(st[1], dA1, du * Bv.y);
            st[2] = fmaf(st[2], dA2, du * Bv.z);
            st[3] = fmaf(st[3], dA3, du * Bv.w);
            float y = st[0] * Cv.x + st[1] * Cv.y + st[2] * Cv.z + st[3] * Cv.w;
            y += __shfl_xor_sync(0xffffffffu, y, 1);
            y += __shfl_xor_sync(0xffffffffu, y, 2);
            if (q == 0) {
                const float g = sG[cur][l * 32 + c];
                const float sg = g / (1.0f + __expf(-g));
                sY[l * 32 + c] = (y + xv * dv) * sg;
            }
        }
        __syncthreads();

#pragma unroll
        for (int k2 = 0; k2 < 4; k2++) {
            int f = tid + k2 * 128;
            int l = f >> 4;
            int c2 = (f & 15) * 2;
            __half2 p = __floats2half2_rn(sY[l * 32 + c2], sY[l * 32 + c2 + 1]);
            *(__half2*)&g_y16[(size_t)(m0 + l) * II + ibase + c2] = p;
        }
    }
}

// ============================================================================
// kernel_launch
// ============================================================================
extern "C" void kernel_launch(void* const* d_in, const int* in_sizes, int n_in,
                              void* d_out, int out_size) {
    const float* hs      = (const float*)d_in[0];
    const float* W_in    = (const float*)d_in[1];
    const float* conv_w  = (const float*)d_in[2];
    const float* conv_b  = (const float*)d_in[3];
    const float* W_x     = (const float*)d_in[4];
    const float* W_dt    = (const float*)d_in[5];
    const float* dt_bias = (const float*)d_in[6];
    const float* Amat    = (const float*)d_in[7];
    const float* Dvec    = (const float*)d_in[8];
    const float* W_out   = (const float*)d_in[9];
    float* out = (float*)d_out;

    float *proj, *delta, *part;
    cudaGetSymbolAddress((void**)&proj, g_proj);
    cudaGetSymbolAddress((void**)&delta, g_delta);
    cudaGetSymbolAddress((void**)&part, g_part);
    __half *hs16, *Win16, *x16, *Wx16, *sp16, *Wdt16, *y16, *Wout16;
    cudaGetSymbolAddress((void**)&hs16, g_hs16);
    cudaGetSymbolAddress((void**)&Win16, g_Win16);
    cudaGetSymbolAddress((void**)&x16, g_x16);
    cudaGetSymbolAddress((void**)&Wx16, g_Wx16);
    cudaGetSymbolAddress((void**)&sp16, g_sp16);
    cudaGetSymbolAddress((void**)&Wdt16, g_Wdt16);
    cudaGetSymbolAddress((void**)&y16, g_y16);
    cudaGetSymbolAddress((void**)&Wout16, g_Wout16);

    cudaFuncSetAttribute(gemm_mma<0>, cudaFuncAttributeMaxDynamicSharedMemorySize, GEMM_SMEM);
    cudaFuncSetAttribute(gemm_mma<1>, cudaFuncAttributeMaxDynamicSharedMemorySize, GEMM_SMEM);

    // -- launches 1..3: conversions needed before/with in_proj --
    {
        int n4;
        n4 = MTOT * HH / 4;
        convert16_kernel<<<(n4 + 255) / 256, 256>>>((const float4*)hs, (uint2*)hs16, n4);
        n4 = E2 * HH / 4;
        convert16_kernel<<<(n4 + 255) / 256, 256>>>((const float4*)W_in, (uint2*)Win16, n4);
        n4 = PP * II / 4;
        convert16_kernel<<<(n4 + 255) / 256, 256>>>((const float4*)W_x, (uint2*)Wx16, n4);
    }

    // -- launch 4: in_proj GEMM (ncu skip-3 capture lands here) --
    gemm_mma<0><<<dim3(E2 / 128, MTOT / 128, 1), 256, GEMM_SMEM>>>(
        hs16, Win16, HH, proj, E2, 0, nullptr);

    // remaining conversions
    {
        int n4;
        n4 = HH * II / 4;
        convert16_kernel<<<(n4 + 255) / 256, 256>>>((const float4*)W_out, (uint2*)Wout16, n4);
        n4 = II * 32;
        convert_wdt_kernel<<<(n4 + 255) / 256, 256>>>(W_dt, (uint2*)Wdt16);
    }

    // conv + SiLU
    {
        int total = (MTOT / 4) * II;
        conv_silu_kernel<<<(total + 255) / 256, 256>>>(conv_w, conv_b);
    }

    // x_proj split-K(8): partials = x @ W_x^T  (K=3072)
    gemm_mma<0><<<dim3(1, MTOT / 128, SPLITK), 256, GEMM_SMEM>>>(
        x16, Wx16, II, part, PP, (size_t)MTOT * PP, nullptr);
    {
        int n4 = MTOT * PP / 4;
        reduce_ssmp_kernel<<<(n4 + 255) / 256, 256>>>();
    }

    // dt_proj + softplus  (K=128 padded)
    gemm_mma<1><<<dim3(II / 128, MTOT / 128, 1), 256, GEMM_SMEM>>>(
        sp16, Wdt16, 128, delta, II, 0, dt_bias);

    // scan -> y fp16
    scan_kernel<<<192, 128>>>(Amat, Dvec);

    // out_proj: direct write (split-K reverted — R11 showed it regresses)
    gemm_mma<0><<<dim3(HH / 128, MTOT / 128, 1), 256, GEMM_SMEM>>>(
        y16, Wout16, II, out, HH, 0, nullptr);
}

// round 14
// speedup vs baseline: 1.2914x; 1.2841x over previous
#include <cuda_runtime.h>
#include <cuda_fp16.h>
#include <math.h>
#include <stdint.h>

// ---------------- problem constants ----------------
#define BB 2
#define LL 2048
#define HH 1536
#define II 3072
#define NN 16
#define RR 96
#define MTOT 4096
#define E2 6144
#define PP 128
#define SPLITK 8
#define P_CH 16            // scan chunks per batch
#define LC 128             // steps per scan chunk
#define L2E 1.4426950408889634f

// ---------------- fp32 scratch ----------------
__device__ __align__(256) float g_proj[(size_t)MTOT * E2];   // in_proj out; x-half becomes y1 in scan phase 1
__device__ __align__(256) float g_x[(size_t)MTOT * II];
__device__ __align__(256) float g_ssmp[(size_t)MTOT * PP];
__device__ __align__(256) float g_delta[(size_t)MTOT * II];  // delta, overwritten with cumdelta by phase 1
__device__ __align__(256) float g_part[SPLITK * (size_t)MTOT * PP];  // x_proj partials; later scan states
#define S0_OFF ((size_t)BB * P_CH * II * NN)   // offset of S0 region inside g_part (floats)

// ---------------- fp16 scratch ----------------
__device__ __align__(256) __half g_hs16[(size_t)MTOT * HH];
__device__ __align__(256) __half g_Win16[(size_t)E2 * HH];
__device__ __align__(256) __half g_x16[(size_t)MTOT * II];
__device__ __align__(256) __half g_Wx16[(size_t)PP * II];
__device__ __align__(256) __half g_sp16[(size_t)MTOT * PP];
__device__ __align__(256) __half g_Wdt16[(size_t)II * PP];   // K padded 96->128
__device__ __align__(256) __half g_y16[(size_t)MTOT * II];
__device__ __align__(256) __half g_Wout16[(size_t)HH * II];

// ---------------- helpers ----------------
__device__ __forceinline__ float fast_ex2(float x) {
    float r; asm("ex2.approx.f32 %0, %1;" : "=f"(r) : "f"(x)); return r;
}
__device__ __forceinline__ uint32_t smem_u32(const void* p) {
    return (uint32_t)__cvta_generic_to_shared(p);
}
__device__ __forceinline__ void cp16(void* dst_smem, const void* src_gmem) {
    unsigned d = smem_u32(dst_smem);
    asm volatile("cp.async.cg.shared.global [%0], [%1], 16;" :: "r"(d), "l"(src_gmem));
}
__device__ __forceinline__ void cp_commit() { asm volatile("cp.async.commit_group;"); }
__device__ __forceinline__ void cp_wait1() { asm volatile("cp.async.wait_group 1;" ::: "memory"); }
__device__ __forceinline__ void cp_wait0() { asm volatile("cp.async.wait_group 0;" ::: "memory"); }

__device__ __forceinline__ void ldsm4(uint32_t& r0, uint32_t& r1, uint32_t& r2, uint32_t& r3,
                                      uint32_t addr) {
    asm volatile("ldmatrix.sync.aligned.m8n8.x4.shared.b16 {%0,%1,%2,%3}, [%4];"
                 : "=r"(r0), "=r"(r1), "=r"(r2), "=r"(r3) : "r"(addr));
}
__device__ __forceinline__ void mma16816(float* d, const uint32_t* a, const uint32_t* b) {
    asm volatile("mma.sync.aligned.m16n8k16.row.col.f32.f16.f16.f32 "
                 "{%0,%1,%2,%3}, {%4,%5,%6,%7}, {%8,%9}, {%0,%1,%2,%3};"
                 : "+f"(d[0]), "+f"(d[1]), "+f"(d[2]), "+f"(d[3])
                 : "r"(a[0]), "r"(a[1]), "r"(a[2]), "r"(a[3]), "r"(b[0]), "r"(b[1]));
}
__device__ __forceinline__ uint32_t pack2(float a, float b) {
    __half2 h = __floats2half2_rn(a, b);
    return *(uint32_t*)&h;
}

// ============================================================================
// fp16 single-pass GEMM (R9 body): C[M,N] = A[M,K]*B[N,K]^T, fp32 accum.
// 128x128 CTA tile, BK=64, 3-stage cp.async, 8 warps (2m x 4n), warp 64x32.
// __launch_bounds__(256, 2). Split-K via blockIdx.z.
// EPI==1: softplus(C + bias[col]).
// ============================================================================
#define TILE_B 16384
#define STAGE_B (2 * TILE_B)
#define GEMM_SMEM (3 * STAGE_B)

template <int EPI>
__global__ __launch_bounds__(256, 2)
void gemm_mma(const __half* __restrict__ A, const __half* __restrict__ B,
              int K, float* __restrict__ C, int ldc,
              size_t c_part_stride, const float* __restrict__ bias) {
    extern __shared__ char smem[];
    const int tid = threadIdx.x;
    const int lane = tid & 31;
    const int wid = tid >> 5;
    const int m0 = blockIdx.y * 128;
    const int n0 = blockIdx.x * 128;
    const int wm = (wid & 1) * 64;
    const int wn = (wid >> 1) * 32;
    const int ncz = (K >> 6) / gridDim.z;
    const int c0 = blockIdx.z * ncz;
    C += (size_t)blockIdx.z * c_part_stride;

    float acc[4][4][4] = {};

    auto issue = [&](int lc) {
        char* st = smem + (lc % 3) * STAGE_B;
        const int k0 = (c0 + lc) << 6;
#pragma unroll
        for (int rep = 0; rep < 4; rep++) {
            int idx = tid + rep * 256;
            int r = idx >> 3;
            int cc = idx & 7;
            uint32_t so = (uint32_t)(r * 128 + ((cc ^ (r & 7)) * 16));
            cp16(st + so, A + (size_t)(m0 + r) * K + k0 + cc * 8);
            cp16(st + TILE_B + so, B + (size_t)(n0 + r) * K + k0 + cc * 8);
        }
    };

    issue(0); cp_commit();
    if (ncz > 1) issue(1);
    cp_commit();

    const int a_row = lane & 15;
    const int a_kh = lane >> 4;
    const int b_nr = (lane & 7) + ((lane >> 4) << 3);
    const int b_kh = (lane >> 3) & 1;

    for (int lc = 0; lc < ncz; lc++) {
        cp_wait1();
        __syncthreads();
        if (lc + 2 < ncz) issue(lc + 2);
        cp_commit();

        const uint32_t sA = smem_u32(smem + (lc % 3) * STAGE_B);
        const uint32_t sB = sA + TILE_B;

#pragma unroll
        for (int kc = 0; kc < 8; kc += 2) {
            uint32_t bf[4][2];
            uint32_t af[4][4];
#pragma unroll
            for (int jj = 0; jj < 2; jj++) {
                int r = wn + b_nr + jj * 16;
                uint32_t off = (uint32_t)(r * 128 + (((kc + b_kh) ^ (r & 7)) * 16));
                uint32_t t0, t1, t2, t3;
                ldsm4(t0, t1, t2, t3, sB + off);
                bf[jj * 2][0] = t0; bf[jj * 2][1] = t1;
                bf[jj * 2 + 1][0] = t2; bf[jj * 2 + 1][1] = t3;
            }
#pragma unroll
            for (int i = 0; i < 4; i++) {
                int r = wm + i * 16 + a_row;
                uint32_t off = (uint32_t)(r * 128 + (((kc + a_kh) ^ (r & 7)) * 16));
                ldsm4(af[i][0], af[i][1], af[i][2], af[i][3], sA + off);
            }
#pragma unroll
            for (int i = 0; i < 4; i++)
#pragma unroll
                for (int j = 0; j < 4; j++)
                    mma16816(acc[i][j], af[i], bf[j]);
        }
    }

    const int quad = lane >> 2;
    const int tq = lane & 3;
#pragma unroll
    for (int i = 0; i < 4; i++) {
#pragma unroll
        for (int j = 0; j < 4; j++) {
            int r0 = m0 + wm + i * 16 + quad;
            int cc = n0 + wn + j * 8 + tq * 2;
            float v0 = acc[i][j][0], v1 = acc[i][j][1];
            float v2 = acc[i][j][2], v3 = acc[i][j][3];
            if (EPI == 1) {
                float b0 = bias[cc], b1 = bias[cc + 1];
                v0 += b0; v1 += b1; v2 += b0; v3 += b1;
                v0 = (v0 > 20.0f) ? v0 : log1pf(__expf(v0));
                v1 = (v1 > 20.0f) ? v1 : log1pf(__expf(v1));
                v2 = (v2 > 20.0f) ? v2 : log1pf(__expf(v2));
                v3 = (v3 > 20.0f) ? v3 : log1pf(__expf(v3));
            }
            *(float2*)(C + (size_t)r0 * ldc + cc) = make_float2(v0, v1);
            *(float2*)(C + (size_t)(r0 + 8) * ldc + cc) = make_float2(v2, v3);
        }
    }
}

// ============================================================================
// conversion kernels
// ============================================================================
__global__ void convert16_kernel(const float4* __restrict__ src,
                                 uint2* __restrict__ dst, int n4) {
    int i = blockIdx.x * blockDim.x + threadIdx.x;
    if (i >= n4) return;
    float4 v = src[i];
    uint2 o;
    o.x = pack2(v.x, v.y);
    o.y = pack2(v.z, v.w);
    dst[i] = o;
}

__global__ void convert_wdt_kernel(const float* __restrict__ src,
                                   uint2* __restrict__ dst) {
    int idx = blockIdx.x * blockDim.x + threadIdx.x;
    if (idx >= II * 32) return;
    int k4 = (idx & 31) * 4;
    int i = idx >> 5;
    float v[4];
#pragma unroll
    for (int t = 0; t < 4; t++)
        v[t] = (k4 + t < RR) ? src[i * RR + k4 + t] : 0.0f;
    uint2 o;
    o.x = pack2(v[0], v[1]);
    o.y = pack2(v[2], v[3]);
    dst[idx] = o;
}

__global__ void reduce_ssmp_kernel() {
    int idx = blockIdx.x * blockDim.x + threadIdx.x;
    if (idx >= MTOT * PP / 4) return;
    const size_t s4 = (size_t)MTOT * PP / 4;
    const float4* p = (const float4*)g_part;
    float4 a = p[idx];
#pragma unroll
    for (int z = 1; z < SPLITK; z++) {
        float4 b = p[z * s4 + idx];
        a.x += b.x; a.y += b.y; a.z += b.z; a.w += b.w;
    }
    ((float4*)g_ssmp)[idx] = a;
    uint2 o; o.x = pack2(a.x, a.y); o.y = pack2(a.z, a.w);
    ((uint2*)g_sp16)[idx] = o;
}

// ============================================================================
// causal depthwise conv1d (K=4) + SiLU; 4 timesteps per thread
// ============================================================================
__global__ void conv_silu_kernel(const float* __restrict__ conv_w,
                                 const float* __restrict__ conv_b) {
    int idx = blockIdx.x * blockDim.x + threadIdx.x;
    if (idx >= (MTOT / 4) * II) return;
    const int i = idx % II;
    const int t = idx / II;
    const int m0 = t * 4;
    const int l0 = m0 & (LL - 1);

    float w0 = conv_w[i * 4 + 0], w1 = conv_w[i * 4 + 1];
    float w2 = conv_w[i * 4 + 2], w3 = conv_w[i * 4 + 3];
    const float cb = conv_b[i];

    float v[7];
#pragma unroll
    for (int j = 0; j < 7; j++) {
        int l = l0 - 3 + j;
        v[j] = (l >= 0) ? g_proj[(size_t)(m0 - 3 + j) * E2 + i] : 0.0f;
    }
#pragma unroll
    for (int s = 0; s < 4; s++) {
        float acc = fmaf(v[s], w0, fmaf(v[s + 1], w1, fmaf(v[s + 2], w2, fmaf(v[s + 3], w3, cb))));
        float o = acc / (1.0f + __expf(-acc));
        size_t off = (size_t)(m0 + s) * II + i;
        g_x[off] = o;
        g_x16[off] = __float2half(o);
    }
}

// ============================================================================
// Scan phase 1: per-chunk local scans (zero initial state).
// Grid: BB*P_CH*96 = 3072 blocks x 128 threads. Block = (batch, chunk, 32 ch).
// Outputs: y1 = C.u + x*D  -> g_proj x-half (fp32)
//          cumdelta        -> g_delta (overwrite, chunk-local)
//          final state u_T -> g_part[0 .. S0_OFF)
// ============================================================================
#define SCH 32

__global__ __launch_bounds__(128)
void scan_phase1(const float* __restrict__ Amat, const float* __restrict__ Dvec) {
    __shared__ __align__(16) float sD[2][SCH * 32];
    __shared__ __align__(16) float sX[2][SCH * 32];
    __shared__ __align__(16) float sBC[2][SCH * 32];
    __shared__ __align__(16) float sY[SCH * 32];
    __shared__ __align__(16) float sCD[SCH * 32];

    const int tid = threadIdx.x;
    const int blk = blockIdx.x;            // 0..3071
    const int b = blk / (P_CH * 96);
    const int rem = blk % (P_CH * 96);
    const int ch = rem / 96;
    const int ibase = (rem % 96) * 32;
    const int q = tid & 3;
    const int c = tid >> 2;
    const int i = ibase + c;
    const int mbase = b * LL + ch * LC;

    float a2[4];
#pragma unroll
    for (int n = 0; n < 4; n++)
        a2[n] = Amat[i * NN + q * 4 + n] * L2E;
    const float dv = Dvec[i];
    float st[4] = {0.0f, 0.0f, 0.0f, 0.0f};
    float cd = 0.0f;

    auto issue = [&](int buf, int sub) {
        const int m0 = mbase + sub * SCH;
#pragma unroll
        for (int k2 = 0; k2 < 2; k2++) {
            int f = tid + k2 * 128;
            int l = f >> 3;
            int c4 = (f & 7) * 4;
            int m = m0 + l;
            cp16(&sD[buf][l * 32 + c4], &g_delta[(size_t)m * II + ibase + c4]);
            cp16(&sX[buf][l * 32 + c4], &g_x[(size_t)m * II + ibase + c4]);
            cp16(&sBC[buf][l * 32 + c4], &g_ssmp[(size_t)m * PP + RR + c4]);
        }
    };

    issue(0, 0);
    cp_commit();

    const int NSUB = LC / SCH;   // 4
    for (int sub = 0; sub < NSUB; sub++) {
        const int cur = sub & 1;
        if (sub + 1 < NSUB) {
            issue(1 - cur, sub + 1);
            cp_commit();
            cp_wait1();
        } else {
            cp_wait0();
        }
        __syncthreads();

        const int m0 = mbase + sub * SCH;
#pragma unroll 4
        for (int l = 0; l < SCH; l++) {
            const float delta = sD[cur][l * 32 + c];
            const float xv = sX[cur][l * 32 + c];
            cd += delta;
            const float du = delta * xv;
            const float4 Bv = *(const float4*)&sBC[cur][l * 32 + q * 4];
            const float4 Cv = *(const float4*)&sBC[cur][l * 32 + 16 + q * 4];
            float dA0 = fast_ex2(delta * a2[0]);
            float dA1 = fast_ex2(delta * a2[1]);
            float dA2 = fast_ex2(delta * a2[2]);
            float dA3 = fast_ex2(delta * a2[3]);
            st[0] = fmaf(st[0], dA0, du * Bv.x);
            st[1] = fmaf(st[1], dA1, du * Bv.y);
            st[2] = fmaf(st[2], dA2, du * Bv.z);
            st[3] = fmaf(st[3], dA3, du * Bv.w);
            float y = st[0] * Cv.x + st[1] * Cv.y + st[2] * Cv.z + st[3] * Cv.w;
            y += __shfl_xor_sync(0xffffffffu, y, 1);
            y += __shfl_xor_sync(0xffffffffu, y, 2);
            if (q == 0) {
                sY[l * 32 + c] = y + xv * dv;
                sCD[l * 32 + c] = cd;
            }
        }
        __syncthreads();

        // cooperative stores: y1 -> g_proj x-half, cumdelta -> g_delta
#pragma unroll
        for (int k2 = 0; k2 < 2; k2++) {
            int f = tid + k2 * 128;
            int l = f >> 3;
            int c4 = (f & 7) * 4;
            int m = m0 + l;
            *(float4*)&g_proj[(size_t)m * E2 + ibase + c4] = *(const float4*)&sY[l * 32 + c4];
            *(float4*)&g_delta[(size_t)m * II + ibase + c4] = *(const float4*)&sCD[l * 32 + c4];
        }
        __syncthreads();  // protect sY/sCD before next sub-chunk rewrites
    }

    // final chunk state u_T
    {
        size_t sidx = (((size_t)(b * P_CH + ch) * II) + i) * NN + q * 4;
        float4 o; o.x = st[0]; o.y = st[1]; o.z = st[2]; o.w = st[3];
        *(float4*)&g_part[sidx] = o;
    }
}

// ============================================================================
// Scan phase 2: sequential state handoff across P_CH chunks (16 steps).
// One thread per (b, i, n). Stores the INCOMING state S0 of each chunk.
// ============================================================================
__global__ void scan_phase2(const float* __restrict__ Amat) {
    int t = blockIdx.x * blockDim.x + threadIdx.x;
    if (t >= BB * II * NN) return;
    const int n = t & (NN - 1);
    const int i = (t >> 4) % II;
    const int b = t / (II * NN);
    const float a2 = Amat[i * NN + n] * L2E;
    float S = 0.0f;
#pragma unroll
    for (int ci = 0; ci < P_CH; ci++) {
        size_t base = (((size_t)(b * P_CH + ci) * II) + i) * NN + n;
        g_part[S0_OFF + base] = S;   // incoming state for chunk ci
        float cdT = g_delta[((size_t)(b * LL + ci * LC + LC - 1)) * II + i];
        float uT = g_part[base];
        S = fast_ex2(a2 * cdT) * S + uT;
    }
}

// ============================================================================
// Scan phase 3: y = (y1 + sum_n C_n * exp(A_n cd) * S0_n) * silu(gate) -> y16.
// Grid: (II/256, MTOT/4), 256 threads. Thread = one i, 4 consecutive m.
// ============================================================================
__global__ __launch_bounds__(256)
void scan_phase3(const float* __restrict__ Amat) {
    __shared__ float sC[4][NN];
    const int i = blockIdx.x * 256 + threadIdx.x;
    const int m0 = blockIdx.y * 4;
    const int b = m0 / LL;
    const int ch = (m0 % LL) / LC;

    if (threadIdx.x < 64) {
        int mm = threadIdx.x >> 4;
        int n = threadIdx.x & 15;
        sC[mm][n] = g_ssmp[(size_t)(m0 + mm) * PP + RR + NN + n];
    }
    __syncthreads();

    float a2[NN], S0[NN];
#pragma unroll
    for (int n4 = 0; n4 < 4; n4++) {
        float4 av = *(const float4*)&Amat[i * NN + n4 * 4];
        a2[n4 * 4 + 0] = av.x * L2E;
        a2[n4 * 4 + 1] = av.y * L2E;
        a2[n4 * 4 + 2] = av.z * L2E;
        a2[n4 * 4 + 3] = av.w * L2E;
    }
    const size_t sbase = (((size_t)(b * P_CH + ch) * II) + i) * NN;
#pragma unroll
    for (int n4 = 0; n4 < 4; n4++)
        *(float4*)&S0[n4 * 4] = *(const float4*)&g_part[S0_OFF + sbase + n4 * 4];

#pragma unroll
    for (int mm = 0; mm < 4; mm++) {
        const int m = m0 + mm;
        const float cd = g_delta[(size_t)m * II + i];
        float corr = 0.0f;
#pragma unroll
        for (int n = 0; n < NN; n++)
            corr = fmaf(sC[mm][n] * fast_ex2(a2[n] * cd), S0[n], corr);
        const float y1 = g_proj[(size_t)m * E2 + i];
        const float g = g_proj[(size_t)m * E2 + II + i];
        const float y = (y1 + corr) * (g / (1.0f + __expf(-g)));
        g_y16[(size_t)m * II + i] = __float2half(y);
    }
}

// ============================================================================
// kernel_launch
// ============================================================================
extern "C" void kernel_launch(void* const* d_in, const int* in_sizes, int n_in,
                              void* d_out, int out_size) {
    const float* hs      = (const float*)d_in[0];
    const float* W_in    = (const float*)d_in[1];
    const float* conv_w  = (const float*)d_in[2];
    const float* conv_b  = (const float*)d_in[3];
    const float* W_x     = (const float*)d_in[4];
    const float* W_dt    = (const float*)d_in[5];
    const float* dt_bias = (const float*)d_in[6];
    const float* Amat    = (const float*)d_in[7];
    const float* Dvec    = (const float*)d_in[8];
    const float* W_out   = (const float*)d_in[9];
    float* out = (float*)d_out;

    float *proj, *delta, *part;
    cudaGetSymbolAddress((void**)&proj, g_proj);
    cudaGetSymbolAddress((void**)&delta, g_delta);
    cudaGetSymbolAddress((void**)&part, g_part);
    __half *hs16, *Win16, *x16, *Wx16, *sp16, *Wdt16, *y16, *Wout16;
    cudaGetSymbolAddress((void**)&hs16, g_hs16);
    cudaGetSymbolAddress((void**)&Win16, g_Win16);
    cudaGetSymbolAddress((void**)&x16, g_x16);
    cudaGetSymbolAddress((void**)&Wx16, g_Wx16);
    cudaGetSymbolAddress((void**)&sp16, g_sp16);
    cudaGetSymbolAddress((void**)&Wdt16, g_Wdt16);
    cudaGetSymbolAddress((void**)&y16, g_y16);
    cudaGetSymbolAddress((void**)&Wout16, g_Wout16);

    cudaFuncSetAttribute(gemm_mma<0>, cudaFuncAttributeMaxDynamicSharedMemorySize, GEMM_SMEM);
    cudaFuncSetAttribute(gemm_mma<1>, cudaFuncAttributeMaxDynamicSharedMemorySize, GEMM_SMEM);

    // -- launches 1..3: conversions needed before in_proj --
    {
        int n4;
        n4 = MTOT * HH / 4;
        convert16_kernel<<<(n4 + 255) / 256, 256>>>((const float4*)hs, (uint2*)hs16, n4);
        n4 = E2 * HH / 4;
        convert16_kernel<<<(n4 + 255) / 256, 256>>>((const float4*)W_in, (uint2*)Win16, n4);
        n4 = PP * II / 4;
        convert16_kernel<<<(n4 + 255) / 256, 256>>>((const float4*)W_x, (uint2*)Wx16, n4);
    }

    // -- launch 4: in_proj GEMM (profiled launch) --
    gemm_mma<0><<<dim3(E2 / 128, MTOT / 128, 1), 256, GEMM_SMEM>>>(
        hs16, Win16, HH, proj, E2, 0, nullptr);

    // remaining conversions
    {
        int n4;
        n4 = HH * II / 4;
        convert16_kernel<<<(n4 + 255) / 256, 256>>>((const float4*)W_out, (uint2*)Wout16, n4);
        n4 = II * 32;
        convert_wdt_kernel<<<(n4 + 255) / 256, 256>>>(W_dt, (uint2*)Wdt16);
    }

    // conv + SiLU
    {
        int total = (MTOT / 4) * II;
        conv_silu_kernel<<<(total + 255) / 256, 256>>>(conv_w, conv_b);
    }

    // x_proj split-K(8)
    gemm_mma<0><<<dim3(1, MTOT / 128, SPLITK), 256, GEMM_SMEM>>>(
        x16, Wx16, II, part, PP, (size_t)MTOT * PP, nullptr);
    {
        int n4 = MTOT * PP / 4;
        reduce_ssmp_kernel<<<(n4 + 255) / 256, 256>>>();
    }

    // dt_proj + softplus  (K=128 padded)
    gemm_mma<1><<<dim3(II / 128, MTOT / 128, 1), 256, GEMM_SMEM>>>(
        sp16, Wdt16, 128, delta, II, 0, dt_bias);

    // chunk-parallel scan
    scan_phase1<<<BB * P_CH * 96, 128>>>(Amat, Dvec);
    scan_phase2<<<(BB * II * NN + 255) / 256, 256>>>(Amat);
    scan_phase3<<<dim3(II / 256, MTOT / 4), 256>>>(Amat);

    // out_proj
    gemm_mma<0><<<dim3(HH / 128, MTOT / 128, 1), 256, GEMM_SMEM>>>(
        y16, Wout16, II, out, HH, 0, nullptr);
}

// round 16
// speedup vs baseline: 1.3091x; 1.0137x over previous
#include <cuda_runtime.h>
#include <cuda_fp16.h>
#include <math.h>
#include <stdint.h>

// ---------------- problem constants ----------------
#define BB 2
#define LL 2048
#define HH 1536
#define II 3072
#define NN 16
#define RR 96
#define MTOT 4096
#define E2 6144
#define PP 128
#define SPLITK 8
#define P_CH 16            // scan chunks per batch
#define LC 128             // steps per scan chunk
#define L2E 1.4426950408889634f

// ---------------- fp32 scratch ----------------
__device__ __align__(256) float g_y1[(size_t)MTOT * II];     // phase1 y1 output (fp32)
__device__ __align__(256) float g_ssmp[(size_t)MTOT * PP];
__device__ __align__(256) float g_cd[(size_t)MTOT * II];     // cumdelta (fp32)
__device__ __align__(256) float g_part[SPLITK * (size_t)MTOT * PP];  // x_proj partials; later scan states
#define S0_OFF ((size_t)BB * P_CH * II * NN)   // offset of S0 region inside g_part (floats)

// ---------------- fp16 scratch ----------------
__device__ __align__(256) __half g_proj16[(size_t)MTOT * E2];   // in_proj out (x | gate), fp16
__device__ __align__(256) __half g_delta16[(size_t)MTOT * II];  // softplus(dt+bias), fp16
__device__ __align__(256) __half g_hs16[(size_t)MTOT * HH];
__device__ __align__(256) __half g_Win16[(size_t)E2 * HH];
__device__ __align__(256) __half g_x16[(size_t)MTOT * II];
__device__ __align__(256) __half g_Wx16[(size_t)PP * II];
__device__ __align__(256) __half g_sp16[(size_t)MTOT * PP];
__device__ __align__(256) __half g_Wdt16[(size_t)II * PP];   // K padded 96->128
__device__ __align__(256) __half g_y16[(size_t)MTOT * II];
__device__ __align__(256) __half g_Wout16[(size_t)HH * II];

// ---------------- helpers ----------------
__device__ __forceinline__ float fast_ex2(float x) {
    float r; asm("ex2.approx.f32 %0, %1;" : "=f"(r) : "f"(x)); return r;
}
__device__ __forceinline__ uint32_t smem_u32(const void* p) {
    return (uint32_t)__cvta_generic_to_shared(p);
}
__device__ __forceinline__ void cp16(void* dst_smem, const void* src_gmem) {
    unsigned d = smem_u32(dst_smem);
    asm volatile("cp.async.cg.shared.global [%0], [%1], 16;" :: "r"(d), "l"(src_gmem));
}
__device__ __forceinline__ void cp_commit() { asm volatile("cp.async.commit_group;"); }
__device__ __forceinline__ void cp_wait1() { asm volatile("cp.async.wait_group 1;" ::: "memory"); }
__device__ __forceinline__ void cp_wait0() { asm volatile("cp.async.wait_group 0;" ::: "memory"); }

__device__ __forceinline__ void ldsm4(uint32_t& r0, uint32_t& r1, uint32_t& r2, uint32_t& r3,
                                      uint32_t addr) {
    asm volatile("ldmatrix.sync.aligned.m8n8.x4.shared.b16 {%0,%1,%2,%3}, [%4];"
                 : "=r"(r0), "=r"(r1), "=r"(r2), "=r"(r3) : "r"(addr));
}
__device__ __forceinline__ void mma16816(float* d, const uint32_t* a, const uint32_t* b) {
    asm volatile("mma.sync.aligned.m16n8k16.row.col.f32.f16.f16.f32 "
                 "{%0,%1,%2,%3}, {%4,%5,%6,%7}, {%8,%9}, {%0,%1,%2,%3};"
                 : "+f"(d[0]), "+f"(d[1]), "+f"(d[2]), "+f"(d[3])
                 : "r"(a[0]), "r"(a[1]), "r"(a[2]), "r"(a[3]), "r"(b[0]), "r"(b[1]));
}
__device__ __forceinline__ uint32_t pack2(float a, float b) {
    __half2 h = __floats2half2_rn(a, b);
    return *(uint32_t*)&h;
}

// ============================================================================
// fp16 single-pass GEMM (R9 body): C[M,N] = A[M,K]*B[N,K]^T, fp32 accum.
// 128x128 CTA tile, BK=64, 3-stage cp.async, 8 warps (2m x 4n), warp 64x32.
// __launch_bounds__(256, 2). Split-K via blockIdx.z (OUT16=0 path only).
// EPI==1: softplus(C + bias[col]).  OUT16: write __half.
// ============================================================================
#define TILE_B 16384
#define STAGE_B (2 * TILE_B)
#define GEMM_SMEM (3 * STAGE_B)

template <int EPI, int OUT16>
__global__ __launch_bounds__(256, 2)
void gemm_mma(const __half* __restrict__ A, const __half* __restrict__ B,
              int K, void* __restrict__ Cv, int ldc,
              size_t c_part_stride, const float* __restrict__ bias) {
    extern __shared__ char smem[];
    const int tid = threadIdx.x;
    const int lane = tid & 31;
    const int wid = tid >> 5;
    const int m0 = blockIdx.y * 128;
    const int n0 = blockIdx.x * 128;
    const int wm = (wid & 1) * 64;
    const int wn = (wid >> 1) * 32;
    const int ncz = (K >> 6) / gridDim.z;
    const int c0 = blockIdx.z * ncz;

    float acc[4][4][4] = {};

    auto issue = [&](int lc) {
        char* st = smem + (lc % 3) * STAGE_B;
        const int k0 = (c0 + lc) << 6;
#pragma unroll
        for (int rep = 0; rep < 4; rep++) {
            int idx = tid + rep * 256;
            int r = idx >> 3;
            int cc = idx & 7;
            uint32_t so = (uint32_t)(r * 128 + ((cc ^ (r & 7)) * 16));
            cp16(st + so, A + (size_t)(m0 + r) * K + k0 + cc * 8);
            cp16(st + TILE_B + so, B + (size_t)(n0 + r) * K + k0 + cc * 8);
        }
    };

    issue(0); cp_commit();
    if (ncz > 1) issue(1);
    cp_commit();

    const int a_row = lane & 15;
    const int a_kh = lane >> 4;
    const int b_nr = (lane & 7) + ((lane >> 4) << 3);
    const int b_kh = (lane >> 3) & 1;

    for (int lc = 0; lc < ncz; lc++) {
        cp_wait1();
        __syncthreads();
        if (lc + 2 < ncz) issue(lc + 2);
        cp_commit();

        const uint32_t sA = smem_u32(smem + (lc % 3) * STAGE_B);
        const uint32_t sB = sA + TILE_B;

#pragma unroll
        for (int kc = 0; kc < 8; kc += 2) {
            uint32_t bf[4][2];
            uint32_t af[4][4];
#pragma unroll
            for (int jj = 0; jj < 2; jj++) {
                int r = wn + b_nr + jj * 16;
                uint32_t off = (uint32_t)(r * 128 + (((kc + b_kh) ^ (r & 7)) * 16));
                uint32_t t0, t1, t2, t3;
                ldsm4(t0, t1, t2, t3, sB + off);
                bf[jj * 2][0] = t0; bf[jj * 2][1] = t1;
                bf[jj * 2 + 1][0] = t2; bf[jj * 2 + 1][1] = t3;
            }
#pragma unroll
            for (int i = 0; i < 4; i++) {
                int r = wm + i * 16 + a_row;
                uint32_t off = (uint32_t)(r * 128 + (((kc + a_kh) ^ (r & 7)) * 16));
                ldsm4(af[i][0], af[i][1], af[i][2], af[i][3], sA + off);
            }
#pragma unroll
            for (int i = 0; i < 4; i++)
#pragma unroll
                for (int j = 0; j < 4; j++)
                    mma16816(acc[i][j], af[i], bf[j]);
        }
    }

    const int quad = lane >> 2;
    const int tq = lane & 3;
#pragma unroll
    for (int i = 0; i < 4; i++) {
#pragma unroll
        for (int j = 0; j < 4; j++) {
            int r0 = m0 + wm + i * 16 + quad;
            int cc = n0 + wn + j * 8 + tq * 2;
            float v0 = acc[i][j][0], v1 = acc[i][j][1];
            float v2 = acc[i][j][2], v3 = acc[i][j][3];
            if (EPI == 1) {
                float b0 = bias[cc], b1 = bias[cc + 1];
                v0 += b0; v1 += b1; v2 += b0; v3 += b1;
                v0 = (v0 > 20.0f) ? v0 : log1pf(__expf(v0));
                v1 = (v1 > 20.0f) ? v1 : log1pf(__expf(v1));
                v2 = (v2 > 20.0f) ? v2 : log1pf(__expf(v2));
                v3 = (v3 > 20.0f) ? v3 : log1pf(__expf(v3));
            }
            if (OUT16) {
                __half* C16 = (__half*)Cv;
                *(__half2*)(C16 + (size_t)r0 * ldc + cc) = __floats2half2_rn(v0, v1);
                *(__half2*)(C16 + (size_t)(r0 + 8) * ldc + cc) = __floats2half2_rn(v2, v3);
            } else {
                float* C = (float*)Cv + (size_t)blockIdx.z * c_part_stride;
                *(float2*)(C + (size_t)r0 * ldc + cc) = make_float2(v0, v1);
                *(float2*)(C + (size_t)(r0 + 8) * ldc + cc) = make_float2(v2, v3);
            }
        }
    }
}

// ============================================================================
// conversion kernels
// ============================================================================
__global__ void convert16_kernel(const float4* __restrict__ src,
                                 uint2* __restrict__ dst, int n4) {
    int i = blockIdx.x * blockDim.x + threadIdx.x;
    if (i >= n4) return;
    float4 v = src[i];
    uint2 o;
    o.x = pack2(v.x, v.y);
    o.y = pack2(v.z, v.w);
    dst[i] = o;
}

__global__ void convert_wdt_kernel(const float* __restrict__ src,
                                   uint2* __restrict__ dst) {
    int idx = blockIdx.x * blockDim.x + threadIdx.x;
    if (idx >= II * 32) return;
    int k4 = (idx & 31) * 4;
    int i = idx >> 5;
    float v[4];
#pragma unroll
    for (int t = 0; t < 4; t++)
        v[t] = (k4 + t < RR) ? src[i * RR + k4 + t] : 0.0f;
    uint2 o;
    o.x = pack2(v[0], v[1]);
    o.y = pack2(v[2], v[3]);
    dst[idx] = o;
}

__global__ void reduce_ssmp_kernel() {
    int idx = blockIdx.x * blockDim.x + threadIdx.x;
    if (idx >= MTOT * PP / 4) return;
    const size_t s4 = (size_t)MTOT * PP / 4;
    const float4* p = (const float4*)g_part;
    float4 a = p[idx];
#pragma unroll
    for (int z = 1; z < SPLITK; z++) {
        float4 b = p[z * s4 + idx];
        a.x += b.x; a.y += b.y; a.z += b.z; a.w += b.w;
    }
    ((float4*)g_ssmp)[idx] = a;
    uint2 o; o.x = pack2(a.x, a.y); o.y = pack2(a.z, a.w);
    ((uint2*)g_sp16)[idx] = o;
}

// ============================================================================
// causal depthwise conv1d (K=4) + SiLU; fp16 in/out, 2 channels x 4 steps/thread
// ============================================================================
__global__ void conv_silu_kernel(const float* __restrict__ conv_w,
                                 const float* __restrict__ conv_b) {
    int idx = blockIdx.x * blockDim.x + threadIdx.x;
    if (idx >= (MTOT / 4) * (II / 2)) return;
    const int i2 = idx % (II / 2);
    const int t = idx / (II / 2);
    const int m0 = t * 4;
    const int l0 = m0 & (LL - 1);
    const int i = i2 * 2;

    float wa[4], wb[4];
#pragma unroll
    for (int j = 0; j < 4; j++) {
        wa[j] = conv_w[i * 4 + j];
        wb[j] = conv_w[(i + 1) * 4 + j];
    }
    const float cba = conv_b[i], cbb = conv_b[i + 1];

    float va[7], vb[7];
#pragma unroll
    for (int j = 0; j < 7; j++) {
        int l = l0 - 3 + j;
        if (l >= 0) {
            __half2 h = *(const __half2*)&g_proj16[(size_t)(m0 - 3 + j) * E2 + i];
            float2 f = __half22float2(h);
            va[j] = f.x; vb[j] = f.y;
        } else {
            va[j] = 0.0f; vb[j] = 0.0f;
        }
    }
#pragma unroll
    for (int s = 0; s < 4; s++) {
        float aa = cba, ab = cbb;
#pragma unroll
        for (int j = 0; j < 4; j++) {
            aa = fmaf(va[s + j], wa[j], aa);
            ab = fmaf(vb[s + j], wb[j], ab);
        }
        float oa = aa / (1.0f + __expf(-aa));
        float ob = ab / (1.0f + __expf(-ab));
        *(__half2*)&g_x16[(size_t)(m0 + s) * II + i] = __floats2half2_rn(oa, ob);
    }
}

// ============================================================================
// Scan phase 1: per-chunk local scans (zero initial state). fp16 streams.
// Grid: BB*P_CH*96 = 3072 blocks x 128 threads.
// Outputs: y1 (fp32) -> g_y1, cumdelta (fp32) -> g_cd, final state -> g_part.
// ============================================================================
#define SCH 32

__global__ __launch_bounds__(128)
void scan_phase1(const float* __restrict__ Amat, const float* __restrict__ Dvec) {
    __shared__ __align__(16) __half sD16[2][SCH * 32];
    __shared__ __align__(16) __half sX16[2][SCH * 32];
    __shared__ __align__(16) float sBC[2][SCH * 32];
    __shared__ __align__(16) float sY[SCH * 32];
    __shared__ __align__(16) float sCD[SCH * 32];

    const int tid = threadIdx.x;
    const int blk = blockIdx.x;            // 0..3071
    const int b = blk / (P_CH * 96);
    const int rem = blk % (P_CH * 96);
    const int ch = rem / 96;
    const int ibase = (rem % 96) * 32;
    const int q = tid & 3;
    const int c = tid >> 2;
    const int i = ibase + c;
    const int mbase = b * LL + ch * LC;

    float a2[4];
#pragma unroll
    for (int n = 0; n < 4; n++)
        a2[n] = Amat[i * NN + q * 4 + n] * L2E;
    const float dv = Dvec[i];
    float st[4] = {0.0f, 0.0f, 0.0f, 0.0f};
    float cd = 0.0f;

    auto issue = [&](int buf, int sub) {
        const int m0 = mbase + sub * SCH;
        // fp16 tensors: 32 steps x 32 ch x 2B = 2048B = 128 x 16B chunks, 1/thread
        {
            int l = tid >> 2;
            int c8 = (tid & 3) * 8;
            int m = m0 + l;
            cp16(&sD16[buf][l * 32 + c8], &g_delta16[(size_t)m * II + ibase + c8]);
            cp16(&sX16[buf][l * 32 + c8], &g_x16[(size_t)m * II + ibase + c8]);
        }
        // BC fp32: 4096B = 256 x 16B chunks, 2/thread
#pragma unroll
        for (int k2 = 0; k2 < 2; k2++) {
            int f = tid + k2 * 128;
            int l = f >> 3;
            int c4 = (f & 7) * 4;
            int m = m0 + l;
            cp16(&sBC[buf][l * 32 + c4], &g_ssmp[(size_t)m * PP + RR + c4]);
        }
    };

    issue(0, 0);
    cp_commit();

    const int NSUB = LC / SCH;   // 4
    for (int sub = 0; sub < NSUB; sub++) {
        const int cur = sub & 1;
        if (sub + 1 < NSUB) {
            issue(1 - cur, sub + 1);
            cp_commit();
            cp_wait1();
        } else {
            cp_wait0();
        }
        __syncthreads();

        const int m0 = mbase + sub * SCH;
#pragma unroll 4
        for (int l = 0; l < SCH; l++) {
            const float delta = __half2float(sD16[cur][l * 32 + c]);
            const float xv = __half2float(sX16[cur][l * 32 + c]);
            cd += delta;
            const float du = delta * xv;
            const float4 Bv = *(const float4*)&sBC[cur][l * 32 + q * 4];
            const float4 Cv = *(const float4*)&sBC[cur][l * 32 + 16 + q * 4];
            float dA0 = fast_ex2(delta * a2[0]);
            float dA1 = fast_ex2(delta * a2[1]);
            float dA2 = fast_ex2(delta * a2[2]);
            float dA3 = fast_ex2(delta * a2[3]);
            st[0] = fmaf(st[0], dA0, du * Bv.x);
            st[1] = fmaf(st[1], dA1, du * Bv.y);
            st[2] = fmaf(st[2], dA2, du * Bv.z);
            st[3] = fmaf(st[3], dA3, du * Bv.w);
            float y = st[0] * Cv.x + st[1] * Cv.y + st[2] * Cv.z + st[3] * Cv.w;
            y += __shfl_xor_sync(0xffffffffu, y, 1);
            y += __shfl_xor_sync(0xffffffffu, y, 2);
            if (q == 0) {
                sY[l * 32 + c] = y + xv * dv;
                sCD[l * 32 + c] = cd;
            }
        }
        __syncthreads();

        // cooperative stores: y1 -> g_y1, cumdelta -> g_cd (fp32)
#pragma unroll
        for (int k2 = 0; k2 < 2; k2++) {
            int f = tid + k2 * 128;
            int l = f >> 3;
            int c4 = (f & 7) * 4;
            int m = m0 + l;
            *(float4*)&g_y1[(size_t)m * II + ibase + c4] = *(const float4*)&sY[l * 32 + c4];
            *(float4*)&g_cd[(size_t)m * II + ibase + c4] = *(const float4*)&sCD[l * 32 + c4];
        }
        __syncthreads();
    }

    // final chunk state u_T
    {
        size_t sidx = (((size_t)(b * P_CH + ch) * II) + i) * NN + q * 4;
        float4 o; o.x = st[0]; o.y = st[1]; o.z = st[2]; o.w = st[3];
        *(float4*)&g_part[sidx] = o;
    }
}

// ============================================================================
// Scan phase 2: sequential state handoff across P_CH chunks.
// ============================================================================
__global__ void scan_phase2(const float* __restrict__ Amat) {
    int t = blockIdx.x * blockDim.x + threadIdx.x;
    if (t >= BB * II * NN) return;
    const int n = t & (NN - 1);
    const int i = (t >> 4) % II;
    const int b = t / (II * NN);
    const float a2 = Amat[i * NN + n] * L2E;
    float S = 0.0f;
#pragma unroll
    for (int ci = 0; ci < P_CH; ci++) {
        size_t base = (((size_t)(b * P_CH + ci) * II) + i) * NN + n;
        g_part[S0_OFF + base] = S;
        float cdT = g_cd[((size_t)(b * LL + ci * LC + LC - 1)) * II + i];
        float uT = g_part[base];
        S = fast_ex2(a2 * cdT) * S + uT;
    }
}

// ============================================================================
// Scan phase 3: y = (y1 + sum_n C_n exp(A_n cd) S0_n) * silu(gate) -> y16.
// ============================================================================
__global__ __launch_bounds__(256)
void scan_phase3(const float* __restrict__ Amat) {
    __shared__ float sC[4][NN];
    const int i = blockIdx.x * 256 + threadIdx.x;
    const int m0 = blockIdx.y * 4;
    const int b = m0 / LL;
    const int ch = (m0 % LL) / LC;

    if (threadIdx.x < 64) {
        int mm = threadIdx.x >> 4;
        int n = threadIdx.x & 15;
        sC[mm][n] = g_ssmp[(size_t)(m0 + mm) * PP + RR + NN + n];
    }
    __syncthreads();

    float a2[NN], S0[NN];
#pragma unroll
    for (int n4 = 0; n4 < 4; n4++) {
        float4 av = *(const float4*)&Amat[i * NN + n4 * 4];
        a2[n4 * 4 + 0] = av.x * L2E;
        a2[n4 * 4 + 1] = av.y * L2E;
        a2[n4 * 4 + 2] = av.z * L2E;
        a2[n4 * 4 + 3] = av.w * L2E;
    }
    const size_t sbase = (((size_t)(b * P_CH + ch) * II) + i) * NN;
#pragma unroll
    for (int n4 = 0; n4 < 4; n4++)
        *(float4*)&S0[n4 * 4] = *(const float4*)&g_part[S0_OFF + sbase + n4 * 4];

#pragma unroll
    for (int mm = 0; mm < 4; mm++) {
        const int m = m0 + mm;
        const float cd = g_cd[(size_t)m * II + i];
        float corr = 0.0f;
#pragma unroll
        for (int n = 0; n < NN; n++)
            corr = fmaf(sC[mm][n] * fast_ex2(a2[n] * cd), S0[n], corr);
        const float y1 = g_y1[(size_t)m * II + i];
        const float g = __half2float(g_proj16[(size_t)m * E2 + II + i]);
        const float y = (y1 + corr) * (g / (1.0f + __expf(-g)));
        g_y16[(size_t)m * II + i] = __float2half(y);
    }
}

// ============================================================================
// kernel_launch
// ============================================================================
extern "C" void kernel_launch(void* const* d_in, const int* in_sizes, int n_in,
                              void* d_out, int out_size) {
    const float* hs      = (const float*)d_in[0];
    const float* W_in    = (const float*)d_in[1];
    const float* conv_w  = (const float*)d_in[2];
    const float* conv_b  = (const float*)d_in[3];
    const float* W_x     = (const float*)d_in[4];
    const float* W_dt    = (const float*)d_in[5];
    const float* dt_bias = (const float*)d_in[6];
    const float* Amat    = (const float*)d_in[7];
    const float* Dvec    = (const float*)d_in[8];
    const float* W_out   = (const float*)d_in[9];
    float* out = (float*)d_out;

    float *part;
    cudaGetSymbolAddress((void**)&part, g_part);
    __half *proj16, *delta16, *hs16, *Win16, *x16, *Wx16, *sp16, *Wdt16, *y16, *Wout16;
    cudaGetSymbolAddress((void**)&proj16, g_proj16);
    cudaGetSymbolAddress((void**)&delta16, g_delta16);
    cudaGetSymbolAddress((void**)&hs16, g_hs16);
    cudaGetSymbolAddress((void**)&Win16, g_Win16);
    cudaGetSymbolAddress((void**)&x16, g_x16);
    cudaGetSymbolAddress((void**)&Wx16, g_Wx16);
    cudaGetSymbolAddress((void**)&sp16, g_sp16);
    cudaGetSymbolAddress((void**)&Wdt16, g_Wdt16);
    cudaGetSymbolAddress((void**)&y16, g_y16);
    cudaGetSymbolAddress((void**)&Wout16, g_Wout16);

    cudaFuncSetAttribute((const void*)gemm_mma<0, 0>, cudaFuncAttributeMaxDynamicSharedMemorySize, GEMM_SMEM);
    cudaFuncSetAttribute((const void*)gemm_mma<0, 1>, cudaFuncAttributeMaxDynamicSharedMemorySize, GEMM_SMEM);
    cudaFuncSetAttribute((const void*)gemm_mma<1, 1>, cudaFuncAttributeMaxDynamicSharedMemorySize, GEMM_SMEM);

    // -- launches 1..3: conversions needed before in_proj --
    {
        int n4;
        n4 = MTOT * HH / 4;
        convert16_kernel<<<(n4 + 255) / 256, 256>>>((const float4*)hs, (uint2*)hs16, n4);
        n4 = E2 * HH / 4;
        convert16_kernel<<<(n4 + 255) / 256, 256>>>((const float4*)W_in, (uint2*)Win16, n4);
        n4 = PP * II / 4;
        convert16_kernel<<<(n4 + 255) / 256, 256>>>((const float4*)W_x, (uint2*)Wx16, n4);
    }

    // -- launch 4: in_proj GEMM -> fp16 proj (profiled launch) --
    gemm_mma<0, 1><<<dim3(E2 / 128, MTOT / 128, 1), 256, GEMM_SMEM>>>(
        hs16, Win16, HH, proj16, E2, 0, nullptr);

    // remaining conversions
    {
        int n4;
        n4 = HH * II / 4;
        convert16_kernel<<<(n4 + 255) / 256, 256>>>((const float4*)W_out, (uint2*)Wout16, n4);
        n4 = II * 32;
        convert_wdt_kernel<<<(n4 + 255) / 256, 256>>>(W_dt, (uint2*)Wdt16);
    }

    // conv + SiLU -> x16
    {
        int total = (MTOT / 4) * (II / 2);
        conv_silu_kernel<<<(total + 255) / 256, 256>>>(conv_w, conv_b);
    }

    // x_proj split-K(8) -> fp32 partials
    gemm_mma<0, 0><<<dim3(1, MTOT / 128, SPLITK), 256, GEMM_SMEM>>>(
        x16, Wx16, II, part, PP, (size_t)MTOT * PP, nullptr);
    {
        int n4 = MTOT * PP / 4;
        reduce_ssmp_kernel<<<(n4 + 255) / 256, 256>>>();
    }

    // dt_proj + softplus -> fp16 delta  (K=128 padded)
    gemm_mma<1, 1><<<dim3(II / 128, MTOT / 128, 1), 256, GEMM_SMEM>>>(
        sp16, Wdt16, 128, delta16, II, 0, dt_bias);

    // chunk-parallel scan
    scan_phase1<<<BB * P_CH * 96, 128>>>(Amat, Dvec);
    scan_phase2<<<(BB * II * NN + 255) / 256, 256>>>(Amat);
    scan_phase3<<<dim3(II / 256, MTOT / 4), 256>>>(Amat);

    // out_proj -> fp32 out
    gemm_mma<0, 0><<<dim3(HH / 128, MTOT / 128, 1), 256, GEMM_SMEM>>>(
        y16, Wout16, II, out, HH, 0, nullptr);
}

// round 17
// speedup vs baseline: 1.3217x; 1.0096x over previous
#include <cuda_runtime.h>
#include <cuda_fp16.h>
#include <math.h>
#include <stdint.h>

// ---------------- problem constants ----------------
#define BB 2
#define LL 2048
#define HH 1536
#define II 3072
#define NN 16
#define RR 96
#define MTOT 4096
#define E2 6144
#define PP 128
#define SPLITK 8
#define P_CH 16            // scan chunks per batch
#define LC 128             // steps per scan chunk
#define L2E 1.4426950408889634f

// ---------------- fp32 scratch ----------------
__device__ __align__(256) float g_y1[(size_t)MTOT * II];     // phase1 y1 output (fp32)
__device__ __align__(256) float g_ssmp[(size_t)MTOT * PP];
__device__ __align__(256) float g_cd[(size_t)MTOT * II];     // cumdelta (fp32)
__device__ __align__(256) float g_part[SPLITK * (size_t)MTOT * PP];  // x_proj partials; later scan states
#define S0_OFF ((size_t)BB * P_CH * II * NN)   // offset of S0 region inside g_part (floats)

// ---------------- fp16 scratch ----------------
__device__ __align__(256) __half g_proj16[(size_t)MTOT * E2];   // in_proj out (x | gate), fp16
__device__ __align__(256) __half g_delta16[(size_t)MTOT * II];  // softplus(dt+bias), fp16
__device__ __align__(256) __half g_hs16[(size_t)MTOT * HH];
__device__ __align__(256) __half g_Win16[(size_t)E2 * HH];
__device__ __align__(256) __half g_x16[(size_t)MTOT * II];
__device__ __align__(256) __half g_Wx16[(size_t)PP * II];
__device__ __align__(256) __half g_sp16[(size_t)MTOT * PP];
__device__ __align__(256) __half g_Wdt16[(size_t)II * PP];   // K padded 96->128
__device__ __align__(256) __half g_y16[(size_t)MTOT * II];
__device__ __align__(256) __half g_Wout16[(size_t)HH * II];

// ---------------- helpers ----------------
__device__ __forceinline__ float fast_ex2(float x) {
    float r; asm("ex2.approx.f32 %0, %1;" : "=f"(r) : "f"(x)); return r;
}
__device__ __forceinline__ uint32_t smem_u32(const void* p) {
    return (uint32_t)__cvta_generic_to_shared(p);
}
__device__ __forceinline__ void cp16(void* dst_smem, const void* src_gmem) {
    unsigned d = smem_u32(dst_smem);
    asm volatile("cp.async.cg.shared.global [%0], [%1], 16;" :: "r"(d), "l"(src_gmem));
}
__device__ __forceinline__ void cp_commit() { asm volatile("cp.async.commit_group;"); }
__device__ __forceinline__ void cp_wait1() { asm volatile("cp.async.wait_group 1;" ::: "memory"); }
__device__ __forceinline__ void cp_wait0() { asm volatile("cp.async.wait_group 0;" ::: "memory"); }

__device__ __forceinline__ void ldsm4(uint32_t& r0, uint32_t& r1, uint32_t& r2, uint32_t& r3,
                                      uint32_t addr) {
    asm volatile("ldmatrix.sync.aligned.m8n8.x4.shared.b16 {%0,%1,%2,%3}, [%4];"
                 : "=r"(r0), "=r"(r1), "=r"(r2), "=r"(r3) : "r"(addr));
}
__device__ __forceinline__ void mma16816(float* d, const uint32_t* a, const uint32_t* b) {
    asm volatile("mma.sync.aligned.m16n8k16.row.col.f32.f16.f16.f32 "
                 "{%0,%1,%2,%3}, {%4,%5,%6,%7}, {%8,%9}, {%0,%1,%2,%3};"
                 : "+f"(d[0]), "+f"(d[1]), "+f"(d[2]), "+f"(d[3])
                 : "r"(a[0]), "r"(a[1]), "r"(a[2]), "r"(a[3]), "r"(b[0]), "r"(b[1]));
}
__device__ __forceinline__ uint32_t pack2(float a, float b) {
    __half2 h = __floats2half2_rn(a, b);
    return *(uint32_t*)&h;
}

// ============================================================================
// fp16 single-pass GEMM: C[M,N] = A[M,K]*B[N,K]^T, fp32 accum.
// 128x128 CTA tile, BK=64, 3-stage cp.async, 8 warps (2m x 4n), warp 64x32.
// __launch_bounds__(256, 2). Split-K via blockIdx.z (OUT16=0 path only).
// EPI==1: softplus(C + bias[col]).  OUT16: write __half.
// ============================================================================
#define TILE_B 16384
#define STAGE_B (2 * TILE_B)
#define GEMM_SMEM (3 * STAGE_B)

template <int EPI, int OUT16>
__global__ __launch_bounds__(256, 2)
void gemm_mma(const __half* __restrict__ A, const __half* __restrict__ B,
              int K, void* __restrict__ Cv, int ldc,
              size_t c_part_stride, const float* __restrict__ bias) {
    extern __shared__ char smem[];
    const int tid = threadIdx.x;
    const int lane = tid & 31;
    const int wid = tid >> 5;
    const int m0 = blockIdx.y * 128;
    const int n0 = blockIdx.x * 128;
    const int wm = (wid & 1) * 64;
    const int wn = (wid >> 1) * 32;
    const int ncz = (K >> 6) / gridDim.z;
    const int c0 = blockIdx.z * ncz;

    float acc[4][4][4] = {};

    auto issue = [&](int lc) {
        char* st = smem + (lc % 3) * STAGE_B;
        const int k0 = (c0 + lc) << 6;
#pragma unroll
        for (int rep = 0; rep < 4; rep++) {
            int idx = tid + rep * 256;
            int r = idx >> 3;
            int cc = idx & 7;
            uint32_t so = (uint32_t)(r * 128 + ((cc ^ (r & 7)) * 16));
            cp16(st + so, A + (size_t)(m0 + r) * K + k0 + cc * 8);
            cp16(st + TILE_B + so, B + (size_t)(n0 + r) * K + k0 + cc * 8);
        }
    };

    issue(0); cp_commit();
    if (ncz > 1) issue(1);
    cp_commit();

    const int a_row = lane & 15;
    const int a_kh = lane >> 4;
    const int b_nr = (lane & 7) + ((lane >> 4) << 3);
    const int b_kh = (lane >> 3) & 1;

    for (int lc = 0; lc < ncz; lc++) {
        cp_wait1();
        __syncthreads();
        if (lc + 2 < ncz) issue(lc + 2);
        cp_commit();

        const uint32_t sA = smem_u32(smem + (lc % 3) * STAGE_B);
        const uint32_t sB = sA + TILE_B;

#pragma unroll
        for (int kc = 0; kc < 8; kc += 2) {
            uint32_t bf[4][2];
            uint32_t af[4][4];
#pragma unroll
            for (int jj = 0; jj < 2; jj++) {
                int r = wn + b_nr + jj * 16;
                uint32_t off = (uint32_t)(r * 128 + (((kc + b_kh) ^ (r & 7)) * 16));
                uint32_t t0, t1, t2, t3;
                ldsm4(t0, t1, t2, t3, sB + off);
                bf[jj * 2][0] = t0; bf[jj * 2][1] = t1;
                bf[jj * 2 + 1][0] = t2; bf[jj * 2 + 1][1] = t3;
            }
#pragma unroll
            for (int i = 0; i < 4; i++) {
                int r = wm + i * 16 + a_row;
                uint32_t off = (uint32_t)(r * 128 + (((kc + a_kh) ^ (r & 7)) * 16));
                ldsm4(af[i][0], af[i][1], af[i][2], af[i][3], sA + off);
            }
#pragma unroll
            for (int i = 0; i < 4; i++)
#pragma unroll
                for (int j = 0; j < 4; j++)
                    mma16816(acc[i][j], af[i], bf[j]);
        }
    }

    const int quad = lane >> 2;
    const int tq = lane & 3;
#pragma unroll
    for (int i = 0; i < 4; i++) {
#pragma unroll
        for (int j = 0; j < 4; j++) {
            int r0 = m0 + wm + i * 16 + quad;
            int cc = n0 + wn + j * 8 + tq * 2;
            float v0 = acc[i][j][0], v1 = acc[i][j][1];
            float v2 = acc[i][j][2], v3 = acc[i][j][3];
            if (EPI == 1) {
                float b0 = bias[cc], b1 = bias[cc + 1];
                v0 += b0; v1 += b1; v2 += b0; v3 += b1;
                v0 = (v0 > 20.0f) ? v0 : log1pf(__expf(v0));
                v1 = (v1 > 20.0f) ? v1 : log1pf(__expf(v1));
                v2 = (v2 > 20.0f) ? v2 : log1pf(__expf(v2));
                v3 = (v3 > 20.0f) ? v3 : log1pf(__expf(v3));
            }
            if (OUT16) {
                __half* C16 = (__half*)Cv;
                *(__half2*)(C16 + (size_t)r0 * ldc + cc) = __floats2half2_rn(v0, v1);
                *(__half2*)(C16 + (size_t)(r0 + 8) * ldc + cc) = __floats2half2_rn(v2, v3);
            } else {
                float* C = (float*)Cv + (size_t)blockIdx.z * c_part_stride;
                *(float2*)(C + (size_t)r0 * ldc + cc) = make_float2(v0, v1);
                *(float2*)(C + (size_t)(r0 + 8) * ldc + cc) = make_float2(v2, v3);
            }
        }
    }
}

// ============================================================================
// conversion kernels
// ============================================================================
__global__ void convert16_kernel(const float4* __restrict__ src,
                                 uint2* __restrict__ dst, int n4) {
    int i = blockIdx.x * blockDim.x + threadIdx.x;
    if (i >= n4) return;
    float4 v = src[i];
    uint2 o;
    o.x = pack2(v.x, v.y);
    o.y = pack2(v.z, v.w);
    dst[i] = o;
}

__global__ void convert_wdt_kernel(const float* __restrict__ src,
                                   uint2* __restrict__ dst) {
    int idx = blockIdx.x * blockDim.x + threadIdx.x;
    if (idx >= II * 32) return;
    int k4 = (idx & 31) * 4;
    int i = idx >> 5;
    float v[4];
#pragma unroll
    for (int t = 0; t < 4; t++)
        v[t] = (k4 + t < RR) ? src[i * RR + k4 + t] : 0.0f;
    uint2 o;
    o.x = pack2(v[0], v[1]);
    o.y = pack2(v[2], v[3]);
    dst[idx] = o;
}

__global__ void reduce_ssmp_kernel() {
    int idx = blockIdx.x * blockDim.x + threadIdx.x;
    if (idx >= MTOT * PP / 4) return;
    const size_t s4 = (size_t)MTOT * PP / 4;
    const float4* p = (const float4*)g_part;
    float4 a = p[idx];
#pragma unroll
    for (int z = 1; z < SPLITK; z++) {
        float4 b = p[z * s4 + idx];
        a.x += b.x; a.y += b.y; a.z += b.z; a.w += b.w;
    }
    ((float4*)g_ssmp)[idx] = a;
    uint2 o; o.x = pack2(a.x, a.y); o.y = pack2(a.z, a.w);
    ((uint2*)g_sp16)[idx] = o;
}

// ============================================================================
// causal depthwise conv1d (K=4) + SiLU; fp16 in/out, 2 channels x 4 steps/thread
// ============================================================================
__global__ void conv_silu_kernel(const float* __restrict__ conv_w,
                                 const float* __restrict__ conv_b) {
    int idx = blockIdx.x * blockDim.x + threadIdx.x;
    if (idx >= (MTOT / 4) * (II / 2)) return;
    const int i2 = idx % (II / 2);
    const int t = idx / (II / 2);
    const int m0 = t * 4;
    const int l0 = m0 & (LL - 1);
    const int i = i2 * 2;

    float wa[4], wb[4];
#pragma unroll
    for (int j = 0; j < 4; j++) {
        wa[j] = conv_w[i * 4 + j];
        wb[j] = conv_w[(i + 1) * 4 + j];
    }
    const float cba = conv_b[i], cbb = conv_b[i + 1];

    float va[7], vb[7];
#pragma unroll
    for (int j = 0; j < 7; j++) {
        int l = l0 - 3 + j;
        if (l >= 0) {
            __half2 h = *(const __half2*)&g_proj16[(size_t)(m0 - 3 + j) * E2 + i];
            float2 f = __half22float2(h);
            va[j] = f.x; vb[j] = f.y;
        } else {
            va[j] = 0.0f; vb[j] = 0.0f;
        }
    }
#pragma unroll
    for (int s = 0; s < 4; s++) {
        float aa = cba, ab = cbb;
#pragma unroll
        for (int j = 0; j < 4; j++) {
            aa = fmaf(va[s + j], wa[j], aa);
            ab = fmaf(vb[s + j], wb[j], ab);
        }
        float oa = aa / (1.0f + __expf(-aa));
        float ob = ab / (1.0f + __expf(-ab));
        *(__half2*)&g_x16[(size_t)(m0 + s) * II + i] = __floats2half2_rn(oa, ob);
    }
}

// ============================================================================
// Scan phase 1: per-chunk local scans (zero initial state). fp16 streams.
// ============================================================================
#define SCH 32

__global__ __launch_bounds__(128)
void scan_phase1(const float* __restrict__ Amat, const float* __restrict__ Dvec) {
    __shared__ __align__(16) __half sD16[2][SCH * 32];
    __shared__ __align__(16) __half sX16[2][SCH * 32];
    __shared__ __align__(16) float sBC[2][SCH * 32];
    __shared__ __align__(16) float sY[SCH * 32];
    __shared__ __align__(16) float sCD[SCH * 32];

    const int tid = threadIdx.x;
    const int blk = blockIdx.x;            // 0..3071
    const int b = blk / (P_CH * 96);
    const int rem = blk % (P_CH * 96);
    const int ch = rem / 96;
    const int ibase = (rem % 96) * 32;
    const int q = tid & 3;
    const int c = tid >> 2;
    const int i = ibase + c;
    const int mbase = b * LL + ch * LC;

    float a2[4];
#pragma unroll
    for (int n = 0; n < 4; n++)
        a2[n] = Amat[i * NN + q * 4 + n] * L2E;
    const float dv = Dvec[i];
    float st[4] = {0.0f, 0.0f, 0.0f, 0.0f};
    float cd = 0.0f;

    auto issue = [&](int buf, int sub) {
        const int m0 = mbase + sub * SCH;
        {
            int l = tid >> 2;
            int c8 = (tid & 3) * 8;
            int m = m0 + l;
            cp16(&sD16[buf][l * 32 + c8], &g_delta16[(size_t)m * II + ibase + c8]);
            cp16(&sX16[buf][l * 32 + c8], &g_x16[(size_t)m * II + ibase + c8]);
        }
#pragma unroll
        for (int k2 = 0; k2 < 2; k2++) {
            int f = tid + k2 * 128;
            int l = f >> 3;
            int c4 = (f & 7) * 4;
            int m = m0 + l;
            cp16(&sBC[buf][l * 32 + c4], &g_ssmp[(size_t)m * PP + RR + c4]);
        }
    };

    issue(0, 0);
    cp_commit();

    const int NSUB = LC / SCH;   // 4
    for (int sub = 0; sub < NSUB; sub++) {
        const int cur = sub & 1;
        if (sub + 1 < NSUB) {
            issue(1 - cur, sub + 1);
            cp_commit();
            cp_wait1();
        } else {
            cp_wait0();
        }
        __syncthreads();

        const int m0 = mbase + sub * SCH;
#pragma unroll 4
        for (int l = 0; l < SCH; l++) {
            const float delta = __half2float(sD16[cur][l * 32 + c]);
            const float xv = __half2float(sX16[cur][l * 32 + c]);
            cd += delta;
            const float du = delta * xv;
            const float4 Bv = *(const float4*)&sBC[cur][l * 32 + q * 4];
            const float4 Cv = *(const float4*)&sBC[cur][l * 32 + 16 + q * 4];
            float dA0 = fast_ex2(delta * a2[0]);
            float dA1 = fast_ex2(delta * a2[1]);
            float dA2 = fast_ex2(delta * a2[2]);
            float dA3 = fast_ex2(delta * a2[3]);
            st[0] = fmaf(st[0], dA0, du * Bv.x);
            st[1] = fmaf(st[1], dA1, du * Bv.y);
            st[2] = fmaf(st[2], dA2, du * Bv.z);
            st[3] = fmaf(st[3], dA3, du * Bv.w);
            float y = st[0] * Cv.x + st[1] * Cv.y + st[2] * Cv.z + st[3] * Cv.w;
            y += __shfl_xor_sync(0xffffffffu, y, 1);
            y += __shfl_xor_sync(0xffffffffu, y, 2);
            if (q == 0) {
                sY[l * 32 + c] = y + xv * dv;
                sCD[l * 32 + c] = cd;
            }
        }
        __syncthreads();

#pragma unroll
        for (int k2 = 0; k2 < 2; k2++) {
            int f = tid + k2 * 128;
            int l = f >> 3;
            int c4 = (f & 7) * 4;
            int m = m0 + l;
            *(float4*)&g_y1[(size_t)m * II + ibase + c4] = *(const float4*)&sY[l * 32 + c4];
            *(float4*)&g_cd[(size_t)m * II + ibase + c4] = *(const float4*)&sCD[l * 32 + c4];
        }
        __syncthreads();
    }

    {
        size_t sidx = (((size_t)(b * P_CH + ch) * II) + i) * NN + q * 4;
        float4 o; o.x = st[0]; o.y = st[1]; o.z = st[2]; o.w = st[3];
        *(float4*)&g_part[sidx] = o;
    }
}

// ============================================================================
// Scan phase 2: sequential state handoff across P_CH chunks.
// ============================================================================
__global__ void scan_phase2(const float* __restrict__ Amat) {
    int t = blockIdx.x * blockDim.x + threadIdx.x;
    if (t >= BB * II * NN) return;
    const int n = t & (NN - 1);
    const int i = (t >> 4) % II;
    const int b = t / (II * NN);
    const float a2 = Amat[i * NN + n] * L2E;
    float S = 0.0f;
#pragma unroll
    for (int ci = 0; ci < P_CH; ci++) {
        size_t base = (((size_t)(b * P_CH + ci) * II) + i) * NN + n;
        g_part[S0_OFF + base] = S;
        float cdT = g_cd[((size_t)(b * LL + ci * LC + LC - 1)) * II + i];
        float uT = g_part[base];
        S = fast_ex2(a2 * cdT) * S + uT;
    }
}

// ============================================================================
// Scan phase 3: y = (y1 + sum_n C_n exp(A_n cd) S0_n) * silu(gate) -> y16.
// ============================================================================
__global__ __launch_bounds__(256)
void scan_phase3(const float* __restrict__ Amat) {
    __shared__ float sC[4][NN];
    const int i = blockIdx.x * 256 + threadIdx.x;
    const int m0 = blockIdx.y * 4;
    const int b = m0 / LL;
    const int ch = (m0 % LL) / LC;

    if (threadIdx.x < 64) {
        int mm = threadIdx.x >> 4;
        int n = threadIdx.x & 15;
        sC[mm][n] = g_ssmp[(size_t)(m0 + mm) * PP + RR + NN + n];
    }
    __syncthreads();

    float a2[NN], S0[NN];
#pragma unroll
    for (int n4 = 0; n4 < 4; n4++) {
        float4 av = *(const float4*)&Amat[i * NN + n4 * 4];
        a2[n4 * 4 + 0] = av.x * L2E;
        a2[n4 * 4 + 1] = av.y * L2E;
        a2[n4 * 4 + 2] = av.z * L2E;
        a2[n4 * 4 + 3] = av.w * L2E;
    }
    const size_t sbase = (((size_t)(b * P_CH + ch) * II) + i) * NN;
#pragma unroll
    for (int n4 = 0; n4 < 4; n4++)
        *(float4*)&S0[n4 * 4] = *(const float4*)&g_part[S0_OFF + sbase + n4 * 4];

#pragma unroll
    for (int mm = 0; mm < 4; mm++) {
        const int m = m0 + mm;
        const float cd = g_cd[(size_t)m * II + i];
        float corr = 0.0f;
#pragma unroll
        for (int n = 0; n < NN; n++)
            corr = fmaf(sC[mm][n] * fast_ex2(a2[n] * cd), S0[n], corr);
        const float y1 = g_y1[(size_t)m * II + i];
        const float g = __half2float(g_proj16[(size_t)m * E2 + II + i]);
        const float y = (y1 + corr) * (g / (1.0f + __expf(-g)));
        g_y16[(size_t)m * II + i] = __float2half(y);
    }
}

// ============================================================================
// kernel_launch — forked-stream pipeline:
//   main: converts(hs,Win,Wx,Wdt) -> inproj_x -> conv -> xproj -> reduce ->
//         dt -> phase1 -> phase2 -> [join] -> phase3 -> outproj
//   side: [fork] -> inproj_gate -> Wout convert -> [join]
// ============================================================================
extern "C" void kernel_launch(void* const* d_in, const int* in_sizes, int n_in,
                              void* d_out, int out_size) {
    const float* hs      = (const float*)d_in[0];
    const float* W_in    = (const float*)d_in[1];
    const float* conv_w  = (const float*)d_in[2];
    const float* conv_b  = (const float*)d_in[3];
    const float* W_x     = (const float*)d_in[4];
    const float* W_dt    = (const float*)d_in[5];
    const float* dt_bias = (const float*)d_in[6];
    const float* Amat    = (const float*)d_in[7];
    const float* Dvec    = (const float*)d_in[8];
    const float* W_out   = (const float*)d_in[9];
    float* out = (float*)d_out;

    float *part;
    cudaGetSymbolAddress((void**)&part, g_part);
    __half *proj16, *delta16, *hs16, *Win16, *x16, *Wx16, *sp16, *Wdt16, *y16, *Wout16;
    cudaGetSymbolAddress((void**)&proj16, g_proj16);
    cudaGetSymbolAddress((void**)&delta16, g_delta16);
    cudaGetSymbolAddress((void**)&hs16, g_hs16);
    cudaGetSymbolAddress((void**)&Win16, g_Win16);
    cudaGetSymbolAddress((void**)&x16, g_x16);
    cudaGetSymbolAddress((void**)&Wx16, g_Wx16);
    cudaGetSymbolAddress((void**)&sp16, g_sp16);
    cudaGetSymbolAddress((void**)&Wdt16, g_Wdt16);
    cudaGetSymbolAddress((void**)&y16, g_y16);
    cudaGetSymbolAddress((void**)&Wout16, g_Wout16);

    cudaFuncSetAttribute((const void*)gemm_mma<0, 0>, cudaFuncAttributeMaxDynamicSharedMemorySize, GEMM_SMEM);
    cudaFuncSetAttribute((const void*)gemm_mma<0, 1>, cudaFuncAttributeMaxDynamicSharedMemorySize, GEMM_SMEM);
    cudaFuncSetAttribute((const void*)gemm_mma<1, 1>, cudaFuncAttributeMaxDynamicSharedMemorySize, GEMM_SMEM);

    // side stream + fork/join events (host objects; created per call, safe
    // under graph capture; capture replays the recorded graph, not this code)
    cudaStream_t s2;
    cudaStreamCreateWithFlags(&s2, cudaStreamNonBlocking);
    cudaEvent_t evFork, evJoin;
    cudaEventCreateWithFlags(&evFork, cudaEventDisableTiming);
    cudaEventCreateWithFlags(&evJoin, cudaEventDisableTiming);

    // -- main: input/weight conversions needed by both branches --
    {
        int n4;
        n4 = MTOT * HH / 4;
        convert16_kernel<<<(n4 + 255) / 256, 256>>>((const float4*)hs, (uint2*)hs16, n4);
        n4 = E2 * HH / 4;
        convert16_kernel<<<(n4 + 255) / 256, 256>>>((const float4*)W_in, (uint2*)Win16, n4);
        n4 = PP * II / 4;
        convert16_kernel<<<(n4 + 255) / 256, 256>>>((const float4*)W_x, (uint2*)Wx16, n4);
        n4 = II * 32;
        convert_wdt_kernel<<<(n4 + 255) / 256, 256>>>(W_dt, (uint2*)Wdt16);
    }

    // fork side branch
    cudaEventRecord(evFork, 0);
    cudaStreamWaitEvent(s2, evFork, 0);

    // side: in_proj gate half (cols II..2II) + W_out convert
    gemm_mma<0, 1><<<dim3(II / 128, MTOT / 128, 1), 256, GEMM_SMEM, s2>>>(
        hs16, Win16 + (size_t)II * HH, HH, proj16 + II, E2, 0, nullptr);
    {
        int n4 = HH * II / 4;
        convert16_kernel<<<(n4 + 255) / 256, 256, 0, s2>>>(
            (const float4*)W_out, (uint2*)Wout16, n4);
    }
    cudaEventRecord(evJoin, s2);

    // main: in_proj x half (cols 0..II)
    gemm_mma<0, 1><<<dim3(II / 128, MTOT / 128, 1), 256, GEMM_SMEM>>>(
        hs16, Win16, HH, proj16, E2, 0, nullptr);

    // conv + SiLU -> x16
    {
        int total = (MTOT / 4) * (II / 2);
        conv_silu_kernel<<<(total + 255) / 256, 256>>>(conv_w, conv_b);
    }

    // x_proj split-K(8) -> fp32 partials
    gemm_mma<0, 0><<<dim3(1, MTOT / 128, SPLITK), 256, GEMM_SMEM>>>(
        x16, Wx16, II, part, PP, (size_t)MTOT * PP, nullptr);
    {
        int n4 = MTOT * PP / 4;
        reduce_ssmp_kernel<<<(n4 + 255) / 256, 256>>>();
    }

    // dt_proj + softplus -> fp16 delta  (K=128 padded)
    gemm_mma<1, 1><<<dim3(II / 128, MTOT / 128, 1), 256, GEMM_SMEM>>>(
        sp16, Wdt16, 128, delta16, II, 0, dt_bias);

    // chunk-parallel scan (phases 1,2 don't need gate)
    scan_phase1<<<BB * P_CH * 96, 128>>>(Amat, Dvec);
    scan_phase2<<<(BB * II * NN + 255) / 256, 256>>>(Amat);

    // join side branch (gate + Wout16 ready), then phase 3 + out_proj
    cudaStreamWaitEvent(0, evJoin, 0);
    scan_phase3<<<dim3(II / 256, MTOT / 4), 256>>>(Amat);

    gemm_mma<0, 0><<<dim3(HH / 128, MTOT / 128, 1), 256, GEMM_SMEM>>>(
        y16, Wout16, II, out, HH, 0, nullptr);
}